// round 11
// baseline (speedup 1.0000x reference)
#include <cuda_runtime.h>
#include <cuda_bf16.h>
#include <math.h>

#define BATCH 4
#define SEQ 2048
#define DMODEL 768
#define NHEADS 12
#define DK 64
#define MTOK (BATCH * SEQ)                 // 8192

typedef unsigned int u32;

// Scratch (__device__ globals: allocation-free contract)
__device__ float g_Q[MTOK * DMODEL];
__device__ float g_K[MTOK * DMODEL];
__device__ float g_V[MTOK * DMODEL];
__device__ float g_AO[MTOK * DMODEL];

// ===========================================================================
// Warp-level tensor-core helpers (baseline PTX: sm_80+, compiles for sm_103)
// ===========================================================================
__device__ __forceinline__ u32 smem_u32(const void* p) {
    u32 a;
    asm("{ .reg .u64 t; cvta.to.shared.u64 t, %1; cvt.u32.u64 %0, t; }"
        : "=r"(a) : "l"(p));
    return a;
}

#define LDSM_X4(r0, r1, r2, r3, addr)                                        \
    asm volatile("ldmatrix.sync.aligned.m8n8.x4.shared.b16 {%0,%1,%2,%3}, [%4];" \
        : "=r"(r0), "=r"(r1), "=r"(r2), "=r"(r3) : "r"(addr))

__device__ __forceinline__ void mma_bf16(float* c, const u32* a, u32 b0, u32 b1) {
    asm volatile(
        "mma.sync.aligned.m16n8k16.row.col.f32.bf16.bf16.f32 "
        "{%0,%1,%2,%3}, {%4,%5,%6,%7}, {%8,%9}, {%0,%1,%2,%3};"
        : "+f"(c[0]), "+f"(c[1]), "+f"(c[2]), "+f"(c[3])
        : "r"(a[0]), "r"(a[1]), "r"(a[2]), "r"(a[3]), "r"(b0), "r"(b1));
}

__device__ __forceinline__ u32 pack_bf2(__nv_bfloat16 a, __nv_bfloat16 b) {
    __nv_bfloat162 t; t.x = a; t.y = b;
    return *reinterpret_cast<u32*>(&t);
}
__device__ __forceinline__ void split_f(float x, __nv_bfloat16& h, __nv_bfloat16& l) {
    h = __float2bfloat16(x);
    l = __float2bfloat16(x - __bfloat162float(h));
}

// smem row stride for bf16 tiles (64 data + 8 pad): 144B rows, ldmatrix-friendly
#define TST 72

// ===========================================================================
// Projection GEMM via HMMA: C[M,N] = A[M,K] @ W[K,N] + bias
// M=8192, N=768, K=768. Block 128x128, K-tiles of 64.
// Same warp layout as scores: 8 warps 4(m) x 2(n), warp tile 32x64.
// smem: Ah/Al [128][TST], Wh/Wl [128 n][TST k] (transposed W).
// ===========================================================================
#define PJ_AH 0
#define PJ_AL 18432
#define PJ_WH 36864
#define PJ_WL 55296
#define PJ_SMEM 73728

__global__ __launch_bounds__(256) void proj_tc_kernel(
    const float* __restrict__ A, const float* __restrict__ W,
    const float* __restrict__ bias, float* __restrict__ C)
{
    extern __shared__ char sm[];
    const u32 sb = smem_u32(sm);

    const int block_row = blockIdx.y * 128;
    const int block_col = blockIdx.x * 128;
    const int tid = threadIdx.x;
    const int wid = tid >> 5, lane = tid & 31;
    const int wm = wid & 3, wn = wid >> 2;
    const int lrow = lane & 15, lhalf = lane >> 4;

    float acc[2][8][4];
#pragma unroll
    for (int mi = 0; mi < 2; mi++)
#pragma unroll
        for (int ni = 0; ni < 8; ni++)
#pragma unroll
            for (int j = 0; j < 4; j++) acc[mi][ni][j] = 0.0f;

    for (int kt = 0; kt < DMODEL; kt += 64) {
        // A tile: [128 m][64 k] -> Ah/Al [m][k]
#pragma unroll
        for (int it = 0; it < 8; it++) {
            const int fid = tid + it * 256;
            const int row = fid >> 4, c4 = (fid & 15) * 4;
            float4 a = *(const float4*)&A[(size_t)(block_row + row) * DMODEL + kt + c4];
            __nv_bfloat16 h0, l0, h1, l1, h2, l2, h3, l3;
            split_f(a.x, h0, l0); split_f(a.y, h1, l1);
            split_f(a.z, h2, l2); split_f(a.w, h3, l3);
            const u32 boff = (u32)(row * TST + c4) * 2;
            *(u32*)(sm + PJ_AH + boff)     = pack_bf2(h0, h1);
            *(u32*)(sm + PJ_AH + boff + 4) = pack_bf2(h2, h3);
            *(u32*)(sm + PJ_AL + boff)     = pack_bf2(l0, l1);
            *(u32*)(sm + PJ_AL + boff + 4) = pack_bf2(l2, l3);
        }
        // W tile: [64 k][128 n] -> transposed Wh/Wl [n][k]
#pragma unroll
        for (int it = 0; it < 8; it++) {
            const int fid = tid + it * 256;
            const int kr = fid >> 5, n4 = (fid & 31) * 4;
            float4 w = *(const float4*)&W[(size_t)(kt + kr) * DMODEL + block_col + n4];
            float ww[4] = {w.x, w.y, w.z, w.w};
#pragma unroll
            for (int e = 0; e < 4; e++) {
                __nv_bfloat16 hh, ll;
                split_f(ww[e], hh, ll);
                const u32 boff = (u32)((n4 + e) * TST + kr) * 2;
                *(__nv_bfloat16*)(sm + PJ_WH + boff) = hh;
                *(__nv_bfloat16*)(sm + PJ_WL + boff) = ll;
            }
        }
        __syncthreads();

#pragma unroll
        for (int ks = 0; ks < 4; ks++) {
            const u32 kcol = (u32)(ks * 16 + lhalf * 8);
            u32 ah[2][4], al[2][4];
#pragma unroll
            for (int mi = 0; mi < 2; mi++) {
                const u32 ro = (u32)((wm * 32 + mi * 16 + lrow) * TST);
                u32 ad = sb + PJ_AH + (ro + kcol) * 2;
                LDSM_X4(ah[mi][0], ah[mi][1], ah[mi][2], ah[mi][3], ad);
                ad = sb + PJ_AL + (ro + kcol) * 2;
                LDSM_X4(al[mi][0], al[mi][1], al[mi][2], al[mi][3], ad);
            }
            u32 bhf[4][4], blf[4][4];
#pragma unroll
            for (int np = 0; np < 4; np++) {
                const u32 ro = (u32)((wn * 64 + np * 16 + lrow) * TST);
                u32 bd = sb + PJ_WH + (ro + kcol) * 2;
                LDSM_X4(bhf[np][0], bhf[np][1], bhf[np][2], bhf[np][3], bd);
                bd = sb + PJ_WL + (ro + kcol) * 2;
                LDSM_X4(blf[np][0], blf[np][1], blf[np][2], blf[np][3], bd);
            }
#pragma unroll
            for (int mi = 0; mi < 2; mi++)
#pragma unroll
                for (int np = 0; np < 4; np++)
#pragma unroll
                    for (int sub = 0; sub < 2; sub++) {
                        const int ni = np * 2 + sub;
                        mma_bf16(acc[mi][ni], ah[mi], bhf[np][sub], bhf[np][sub + 2]);
                        mma_bf16(acc[mi][ni], ah[mi], blf[np][sub], blf[np][sub + 2]);
                        mma_bf16(acc[mi][ni], al[mi], bhf[np][sub], bhf[np][sub + 2]);
                    }
        }
        __syncthreads();
    }

    // Epilogue: + bias, fp32 stores
    const int rbase = block_row + wm * 32 + (lane >> 2);
    const int cbase = block_col + wn * 64 + (lane & 3) * 2;
#pragma unroll
    for (int mi = 0; mi < 2; mi++)
#pragma unroll
        for (int half = 0; half < 2; half++) {
            const int r = rbase + mi * 16 + half * 8;
            float* rowp = C + (size_t)r * DMODEL;
#pragma unroll
            for (int ni = 0; ni < 8; ni++) {
                const int c = cbase + ni * 8;
                float2 o;
                o.x = acc[mi][ni][half * 2]     + bias[c];
                o.y = acc[mi][ni][half * 2 + 1] + bias[c + 1];
                *(float2*)&rowp[c] = o;
            }
        }
}

// ===========================================================================
// Scores via HMMA: E[bh,i,j] = exp( <Q_i,K_j> / 8 )  (unnormalized weights)
// ===========================================================================
#define SC_QH 0
#define SC_QL 18432
#define SC_KH 36864
#define SC_KL 55296
#define SC_SMEM 73728

__global__ __launch_bounds__(256) void scores_tc_kernel(
    const float* __restrict__ Q, const float* __restrict__ Km,
    float* __restrict__ attn)
{
    extern __shared__ char sm[];
    const u32 sb = smem_u32(sm);

    const int bh = blockIdx.z;
    const int b = bh / NHEADS, h = bh % NHEADS;
    const float* Qb = Q + (size_t)b * SEQ * DMODEL + h * DK;
    const float* Kb = Km + (size_t)b * SEQ * DMODEL + h * DK;
    float* Sout = attn + (size_t)bh * SEQ * SEQ;

    const int block_row = blockIdx.y * 128;
    const int block_col = blockIdx.x * 128;
    const int tid = threadIdx.x;
    const int wid = tid >> 5, lane = tid & 31;
    const int wm = wid & 3, wn = wid >> 2;

#pragma unroll
    for (int it = 0; it < 8; it++) {
        const int fid = tid + it * 256;
        const int row = fid >> 4, c4 = (fid & 15) * 4;
        const u32 boff = (u32)(row * TST + c4) * 2;

        float4 q = *(const float4*)&Qb[(size_t)(block_row + row) * DMODEL + c4];
        __nv_bfloat16 h0, l0, h1, l1, h2, l2, h3, l3;
        split_f(q.x, h0, l0); split_f(q.y, h1, l1);
        split_f(q.z, h2, l2); split_f(q.w, h3, l3);
        *(u32*)(sm + SC_QH + boff)     = pack_bf2(h0, h1);
        *(u32*)(sm + SC_QH + boff + 4) = pack_bf2(h2, h3);
        *(u32*)(sm + SC_QL + boff)     = pack_bf2(l0, l1);
        *(u32*)(sm + SC_QL + boff + 4) = pack_bf2(l2, l3);

        float4 k = *(const float4*)&Kb[(size_t)(block_col + row) * DMODEL + c4];
        split_f(k.x, h0, l0); split_f(k.y, h1, l1);
        split_f(k.z, h2, l2); split_f(k.w, h3, l3);
        *(u32*)(sm + SC_KH + boff)     = pack_bf2(h0, h1);
        *(u32*)(sm + SC_KH + boff + 4) = pack_bf2(h2, h3);
        *(u32*)(sm + SC_KL + boff)     = pack_bf2(l0, l1);
        *(u32*)(sm + SC_KL + boff + 4) = pack_bf2(l2, l3);
    }
    __syncthreads();

    float acc[2][8][4];
#pragma unroll
    for (int mi = 0; mi < 2; mi++)
#pragma unroll
        for (int ni = 0; ni < 8; ni++)
#pragma unroll
            for (int j = 0; j < 4; j++) acc[mi][ni][j] = 0.0f;

    const int lrow = lane & 15, lhalf = lane >> 4;

#pragma unroll
    for (int ks = 0; ks < 4; ks++) {
        const u32 kcol = (u32)(ks * 16 + lhalf * 8);
        u32 ah[2][4], al[2][4];
#pragma unroll
        for (int mi = 0; mi < 2; mi++) {
            const u32 ro = (u32)((wm * 32 + mi * 16 + lrow) * TST);
            u32 ad = sb + SC_QH + (ro + kcol) * 2;
            LDSM_X4(ah[mi][0], ah[mi][1], ah[mi][2], ah[mi][3], ad);
            ad = sb + SC_QL + (ro + kcol) * 2;
            LDSM_X4(al[mi][0], al[mi][1], al[mi][2], al[mi][3], ad);
        }
        u32 bhf[4][4], blf[4][4];
#pragma unroll
        for (int np = 0; np < 4; np++) {
            const u32 ro = (u32)((wn * 64 + np * 16 + lrow) * TST);
            u32 bd = sb + SC_KH + (ro + kcol) * 2;
            LDSM_X4(bhf[np][0], bhf[np][1], bhf[np][2], bhf[np][3], bd);
            bd = sb + SC_KL + (ro + kcol) * 2;
            LDSM_X4(blf[np][0], blf[np][1], blf[np][2], blf[np][3], bd);
        }
#pragma unroll
        for (int mi = 0; mi < 2; mi++)
#pragma unroll
            for (int np = 0; np < 4; np++)
#pragma unroll
                for (int sub = 0; sub < 2; sub++) {
                    const int ni = np * 2 + sub;
                    mma_bf16(acc[mi][ni], ah[mi], bhf[np][sub], bhf[np][sub + 2]);
                    mma_bf16(acc[mi][ni], ah[mi], blf[np][sub], blf[np][sub + 2]);
                    mma_bf16(acc[mi][ni], al[mi], bhf[np][sub], bhf[np][sub + 2]);
                }
    }

    const float scale = 0.125f;
    const int rbase = block_row + wm * 32 + (lane >> 2);
    const int cbase = block_col + wn * 64 + (lane & 3) * 2;
#pragma unroll
    for (int mi = 0; mi < 2; mi++)
#pragma unroll
        for (int half = 0; half < 2; half++) {
            const int r = rbase + mi * 16 + half * 8;
            float* rowp = Sout + (size_t)r * SEQ;
#pragma unroll
            for (int ni = 0; ni < 8; ni++) {
                float2 e;
                e.x = __expf(scale * acc[mi][ni][half * 2]);
                e.y = __expf(scale * acc[mi][ni][half * 2 + 1]);
                *(float2*)&rowp[cbase + ni * 8] = e;
            }
        }
}

// ===========================================================================
// PV via HMMA, fused softmax-normalize. (unchanged from R10)
// ===========================================================================
#define PV_PH 0
#define PV_PL 18432
#define PV_VTH 36864
#define PV_VTL 46080
#define PV_INV 55296
#define PV_SMEM (55296 + 512)

__global__ __launch_bounds__(256) void pv_tc_kernel(
    float* __restrict__ attn, const float* __restrict__ V,
    float* __restrict__ AO)
{
    extern __shared__ char sm[];
    const u32 sb = smem_u32(sm);
    float* inv_s = (float*)(sm + PV_INV);

    const int bh = blockIdx.z;
    const int b = bh / NHEADS, h = bh % NHEADS;
    const int block_row = blockIdx.y * 128;
    float* Sbase = attn + (size_t)bh * SEQ * SEQ + (size_t)block_row * SEQ;
    const float* Vb = V + (size_t)b * SEQ * DMODEL + h * DK;
    float* Ob = AO + (size_t)(b * SEQ + block_row) * DMODEL + h * DK;

    const int tid = threadIdx.x;
    const int wid = tid >> 5, lane = tid & 31;
    const int wm = wid & 3, wn = wid >> 2;

    for (int r0 = 0; r0 < 16; r0++) {
        const int row = wid * 16 + r0;
        const float4* Sr = (const float4*)(Sbase + (size_t)row * SEQ);
        float s = 0.0f;
#pragma unroll 4
        for (int it = 0; it < 16; it++) {
            float4 x = Sr[lane + it * 32];
            s += x.x + x.y + x.z + x.w;
        }
#pragma unroll
        for (int off = 16; off > 0; off >>= 1)
            s += __shfl_xor_sync(0xFFFFFFFFu, s, off);
        if (lane == 0) inv_s[row] = 1.0f / s;
    }
    __syncthreads();

    float acc[2][4][4];
#pragma unroll
    for (int mi = 0; mi < 2; mi++)
#pragma unroll
        for (int ni = 0; ni < 4; ni++)
#pragma unroll
            for (int j = 0; j < 4; j++) acc[mi][ni][j] = 0.0f;

    const int lrow = lane & 15, lhalf = lane >> 4;

    for (int t = 0; t < 32; t++) {
        const int k0 = t * 64;

#pragma unroll
        for (int l = 0; l < 8; l++) {
            const int fid = tid + l * 256;
            const int row = fid >> 4, c4 = (fid & 15) * 4;
            float* sp = Sbase + (size_t)row * SEQ + k0 + c4;
            float4 e = *(const float4*)sp;
            const float inv = inv_s[row];
            e.x *= inv; e.y *= inv; e.z *= inv; e.w *= inv;
            *(float4*)sp = e;
            __nv_bfloat16 h0, l0, h1, l1, h2, l2, h3, l3;
            split_f(e.x, h0, l0); split_f(e.y, h1, l1);
            split_f(e.z, h2, l2); split_f(e.w, h3, l3);
            const u32 boff = (u32)(row * TST + c4) * 2;
            *(u32*)(sm + PV_PH + boff)     = pack_bf2(h0, h1);
            *(u32*)(sm + PV_PH + boff + 4) = pack_bf2(h2, h3);
            *(u32*)(sm + PV_PL + boff)     = pack_bf2(l0, l1);
            *(u32*)(sm + PV_PL + boff + 4) = pack_bf2(l2, l3);
        }
#pragma unroll
        for (int l = 0; l < 4; l++) {
            const int fid = tid + l * 256;
            const int kr = fid >> 4, n4 = (fid & 15) * 4;
            float4 v = *(const float4*)&Vb[(size_t)(k0 + kr) * DMODEL + n4];
            float vv[4] = {v.x, v.y, v.z, v.w};
#pragma unroll
            for (int e = 0; e < 4; e++) {
                __nv_bfloat16 hh, ll;
                split_f(vv[e], hh, ll);
                const u32 boff = (u32)((n4 + e) * TST + kr) * 2;
                *(__nv_bfloat16*)(sm + PV_VTH + boff) = hh;
                *(__nv_bfloat16*)(sm + PV_VTL + boff) = ll;
            }
        }
        __syncthreads();

#pragma unroll
        for (int ks = 0; ks < 4; ks++) {
            const u32 kcol = (u32)(ks * 16 + lhalf * 8);
            u32 ah[2][4], al[2][4];
#pragma unroll
            for (int mi = 0; mi < 2; mi++) {
                const u32 ro = (u32)((wm * 32 + mi * 16 + lrow) * TST);
                u32 ad = sb + PV_PH + (ro + kcol) * 2;
                LDSM_X4(ah[mi][0], ah[mi][1], ah[mi][2], ah[mi][3], ad);
                ad = sb + PV_PL + (ro + kcol) * 2;
                LDSM_X4(al[mi][0], al[mi][1], al[mi][2], al[mi][3], ad);
            }
            u32 bhf[2][4], blf[2][4];
#pragma unroll
            for (int np = 0; np < 2; np++) {
                const u32 ro = (u32)((wn * 32 + np * 16 + lrow) * TST);
                u32 bd = sb + PV_VTH + (ro + kcol) * 2;
                LDSM_X4(bhf[np][0], bhf[np][1], bhf[np][2], bhf[np][3], bd);
                bd = sb + PV_VTL + (ro + kcol) * 2;
                LDSM_X4(blf[np][0], blf[np][1], blf[np][2], blf[np][3], bd);
            }
#pragma unroll
            for (int mi = 0; mi < 2; mi++)
#pragma unroll
                for (int np = 0; np < 2; np++)
#pragma unroll
                    for (int sub = 0; sub < 2; sub++) {
                        const int ni = np * 2 + sub;
                        mma_bf16(acc[mi][ni], ah[mi], bhf[np][sub], bhf[np][sub + 2]);
                        mma_bf16(acc[mi][ni], ah[mi], blf[np][sub], blf[np][sub + 2]);
                        mma_bf16(acc[mi][ni], al[mi], bhf[np][sub], bhf[np][sub + 2]);
                    }
        }
        __syncthreads();
    }

    const int rbase = wm * 32 + (lane >> 2);
    const int cbase = wn * 32 + (lane & 3) * 2;
#pragma unroll
    for (int mi = 0; mi < 2; mi++)
#pragma unroll
        for (int half = 0; half < 2; half++) {
            const int r = rbase + mi * 16 + half * 8;
            float* orow = Ob + (size_t)r * DMODEL;
#pragma unroll
            for (int ni = 0; ni < 4; ni++) {
                float2 o;
                o.x = acc[mi][ni][half * 2];
                o.y = acc[mi][ni][half * 2 + 1];
                *(float2*)&orow[cbase + ni * 8] = o;
            }
        }
}

// ===========================================================================
extern "C" void kernel_launch(void* const* d_in, const int* in_sizes, int n_in,
                              void* d_out, int out_size)
{
    const float* query = (const float*)d_in[0];
    const float* key   = (const float*)d_in[1];
    const float* value = (const float*)d_in[2];
    const float* Wq = (const float*)d_in[3];
    const float* bq = (const float*)d_in[4];
    const float* Wk = (const float*)d_in[5];
    const float* bk = (const float*)d_in[6];
    const float* Wv = (const float*)d_in[7];
    const float* bv = (const float*)d_in[8];
    const float* Wo = (const float*)d_in[9];
    const float* bo = (const float*)d_in[10];

    float* out  = (float*)d_out;
    float* attn = out + (size_t)MTOK * DMODEL;

    float *Qp, *Kp, *Vp, *AOp;
    cudaGetSymbolAddress((void**)&Qp,  g_Q);
    cudaGetSymbolAddress((void**)&Kp,  g_K);
    cudaGetSymbolAddress((void**)&Vp,  g_V);
    cudaGetSymbolAddress((void**)&AOp, g_AO);

    static bool attr_done = false;
    if (!attr_done) {
        cudaFuncSetAttribute(proj_tc_kernel,
            cudaFuncAttributeMaxDynamicSharedMemorySize, PJ_SMEM);
        cudaFuncSetAttribute(scores_tc_kernel,
            cudaFuncAttributeMaxDynamicSharedMemorySize, SC_SMEM);
        cudaFuncSetAttribute(pv_tc_kernel,
            cudaFuncAttributeMaxDynamicSharedMemorySize, PV_SMEM);
        attr_done = true;
    }

    dim3 gproj(DMODEL / 128, MTOK / 128);  // (6, 64)
    proj_tc_kernel<<<gproj, 256, PJ_SMEM>>>(query, Wq, bq, Qp);
    proj_tc_kernel<<<gproj, 256, PJ_SMEM>>>(key,   Wk, bk, Kp);
    proj_tc_kernel<<<gproj, 256, PJ_SMEM>>>(value, Wv, bv, Vp);

    dim3 gscores(SEQ / 128, SEQ / 128, BATCH * NHEADS);  // (16, 16, 48)
    scores_tc_kernel<<<gscores, 256, SC_SMEM>>>(Qp, Kp, attn);

    dim3 gpv(1, SEQ / 128, BATCH * NHEADS);  // (1, 16, 48)
    pv_tc_kernel<<<gpv, 256, PV_SMEM>>>(attn, Vp, AOp);

    proj_tc_kernel<<<gproj, 256, PJ_SMEM>>>(AOp, Wo, bo, out);
}

// round 13
// speedup vs baseline: 1.5404x; 1.5404x over previous
#include <cuda_runtime.h>
#include <cuda_bf16.h>
#include <math.h>

#define BATCH 4
#define SEQ 2048
#define DMODEL 768
#define NHEADS 12
#define DK 64
#define MTOK (BATCH * SEQ)                 // 8192
#define ATTN_ROWS (BATCH * NHEADS * SEQ)   // 98304

typedef unsigned int u32;

// Scratch (__device__ globals: allocation-free contract)
__device__ float g_Q[MTOK * DMODEL];
__device__ float g_K[MTOK * DMODEL];
__device__ float g_V[MTOK * DMODEL];
__device__ float g_AO[MTOK * DMODEL];
__device__ float g_rowsum[ATTN_ROWS];

__global__ void init_rowsum_kernel(float* rs) {
    int i = blockIdx.x * blockDim.x + threadIdx.x;
    if (i < ATTN_ROWS) rs[i] = 0.0f;
}

// ===========================================================================
// Warp-level tensor-core helpers (baseline PTX: sm_80+, compiles for sm_103)
// ===========================================================================
__device__ __forceinline__ u32 smem_u32(const void* p) {
    u32 a;
    asm("{ .reg .u64 t; cvta.to.shared.u64 t, %1; cvt.u32.u64 %0, t; }"
        : "=r"(a) : "l"(p));
    return a;
}

#define LDSM_X4(r0, r1, r2, r3, addr)                                        \
    asm volatile("ldmatrix.sync.aligned.m8n8.x4.shared.b16 {%0,%1,%2,%3}, [%4];" \
        : "=r"(r0), "=r"(r1), "=r"(r2), "=r"(r3) : "r"(addr))

__device__ __forceinline__ void mma_bf16(float* c, const u32* a, u32 b0, u32 b1) {
    asm volatile(
        "mma.sync.aligned.m16n8k16.row.col.f32.bf16.bf16.f32 "
        "{%0,%1,%2,%3}, {%4,%5,%6,%7}, {%8,%9}, {%0,%1,%2,%3};"
        : "+f"(c[0]), "+f"(c[1]), "+f"(c[2]), "+f"(c[3])
        : "r"(a[0]), "r"(a[1]), "r"(a[2]), "r"(a[3]), "r"(b0), "r"(b1));
}

__device__ __forceinline__ u32 pack_bf2(__nv_bfloat16 a, __nv_bfloat16 b) {
    __nv_bfloat162 t; t.x = a; t.y = b;
    return *reinterpret_cast<u32*>(&t);
}
__device__ __forceinline__ void split_f(float x, __nv_bfloat16& h, __nv_bfloat16& l) {
    h = __float2bfloat16(x);
    l = __float2bfloat16(x - __bfloat162float(h));
}

// smem row stride for bf16 tiles (64 data + 8 pad): 144B rows, ldmatrix-friendly
#define TST 72

// ===========================================================================
// Projection GEMM via HMMA: C[M,N] = A[M,K] @ W[K,N] + bias
// ===========================================================================
#define PJ_AH 0
#define PJ_AL 18432
#define PJ_WH 36864
#define PJ_WL 55296
#define PJ_SMEM 73728

__global__ __launch_bounds__(256) void proj_tc_kernel(
    const float* __restrict__ A, const float* __restrict__ W,
    const float* __restrict__ bias, float* __restrict__ C)
{
    extern __shared__ char sm[];
    const u32 sb = smem_u32(sm);

    const int block_row = blockIdx.y * 128;
    const int block_col = blockIdx.x * 128;
    const int tid = threadIdx.x;
    const int wid = tid >> 5, lane = tid & 31;
    const int wm = wid & 3, wn = wid >> 2;
    const int lrow = lane & 15, lhalf = lane >> 4;

    float acc[2][8][4];
#pragma unroll
    for (int mi = 0; mi < 2; mi++)
#pragma unroll
        for (int ni = 0; ni < 8; ni++)
#pragma unroll
            for (int j = 0; j < 4; j++) acc[mi][ni][j] = 0.0f;

    for (int kt = 0; kt < DMODEL; kt += 64) {
        // A tile: [128 m][64 k] -> Ah/Al [m][k]
#pragma unroll
        for (int it = 0; it < 8; it++) {
            const int fid = tid + it * 256;
            const int row = fid >> 4, c4 = (fid & 15) * 4;
            float4 a = *(const float4*)&A[(size_t)(block_row + row) * DMODEL + kt + c4];
            __nv_bfloat16 h0, l0, h1, l1, h2, l2, h3, l3;
            split_f(a.x, h0, l0); split_f(a.y, h1, l1);
            split_f(a.z, h2, l2); split_f(a.w, h3, l3);
            const u32 boff = (u32)(row * TST + c4) * 2;
            *(u32*)(sm + PJ_AH + boff)     = pack_bf2(h0, h1);
            *(u32*)(sm + PJ_AH + boff + 4) = pack_bf2(h2, h3);
            *(u32*)(sm + PJ_AL + boff)     = pack_bf2(l0, l1);
            *(u32*)(sm + PJ_AL + boff + 4) = pack_bf2(l2, l3);
        }
        // W tile: [64 k][128 n] -> transposed Wh/Wl [n][k]
#pragma unroll
        for (int it = 0; it < 8; it++) {
            const int fid = tid + it * 256;
            const int kr = fid >> 5, n4 = (fid & 31) * 4;
            float4 w = *(const float4*)&W[(size_t)(kt + kr) * DMODEL + block_col + n4];
            float ww[4] = {w.x, w.y, w.z, w.w};
#pragma unroll
            for (int e = 0; e < 4; e++) {
                __nv_bfloat16 hh, ll;
                split_f(ww[e], hh, ll);
                const u32 boff = (u32)((n4 + e) * TST + kr) * 2;
                *(__nv_bfloat16*)(sm + PJ_WH + boff) = hh;
                *(__nv_bfloat16*)(sm + PJ_WL + boff) = ll;
            }
        }
        __syncthreads();

#pragma unroll
        for (int ks = 0; ks < 4; ks++) {
            const u32 kcol = (u32)(ks * 16 + lhalf * 8);
            u32 ah[2][4], al[2][4];
#pragma unroll
            for (int mi = 0; mi < 2; mi++) {
                const u32 ro = (u32)((wm * 32 + mi * 16 + lrow) * TST);
                u32 ad = sb + PJ_AH + (ro + kcol) * 2;
                LDSM_X4(ah[mi][0], ah[mi][1], ah[mi][2], ah[mi][3], ad);
                ad = sb + PJ_AL + (ro + kcol) * 2;
                LDSM_X4(al[mi][0], al[mi][1], al[mi][2], al[mi][3], ad);
            }
            u32 bhf[4][4], blf[4][4];
#pragma unroll
            for (int np = 0; np < 4; np++) {
                const u32 ro = (u32)((wn * 64 + np * 16 + lrow) * TST);
                u32 bd = sb + PJ_WH + (ro + kcol) * 2;
                LDSM_X4(bhf[np][0], bhf[np][1], bhf[np][2], bhf[np][3], bd);
                bd = sb + PJ_WL + (ro + kcol) * 2;
                LDSM_X4(blf[np][0], blf[np][1], blf[np][2], blf[np][3], bd);
            }
#pragma unroll
            for (int mi = 0; mi < 2; mi++)
#pragma unroll
                for (int np = 0; np < 4; np++)
#pragma unroll
                    for (int sub = 0; sub < 2; sub++) {
                        const int ni = np * 2 + sub;
                        mma_bf16(acc[mi][ni], ah[mi], bhf[np][sub], bhf[np][sub + 2]);
                        mma_bf16(acc[mi][ni], ah[mi], blf[np][sub], blf[np][sub + 2]);
                        mma_bf16(acc[mi][ni], al[mi], bhf[np][sub], bhf[np][sub + 2]);
                    }
        }
        __syncthreads();
    }

    const int rbase = block_row + wm * 32 + (lane >> 2);
    const int cbase = block_col + wn * 64 + (lane & 3) * 2;
#pragma unroll
    for (int mi = 0; mi < 2; mi++)
#pragma unroll
        for (int half = 0; half < 2; half++) {
            const int r = rbase + mi * 16 + half * 8;
            float* rowp = C + (size_t)r * DMODEL;
#pragma unroll
            for (int ni = 0; ni < 8; ni++) {
                const int c = cbase + ni * 8;
                float2 o;
                o.x = acc[mi][ni][half * 2]     + bias[c];
                o.y = acc[mi][ni][half * 2 + 1] + bias[c + 1];
                *(float2*)&rowp[c] = o;
            }
        }
}

// ===========================================================================
// Scores via HMMA: E[bh,i,j] = exp( <Q_i,K_j> / 8 )  + per-row sum atomics
// ===========================================================================
#define SC_QH 0
#define SC_QL 18432
#define SC_KH 36864
#define SC_KL 55296
#define SC_SMEM 73728

__global__ __launch_bounds__(256) void scores_tc_kernel(
    const float* __restrict__ Q, const float* __restrict__ Km,
    float* __restrict__ attn, float* __restrict__ rowsum)
{
    extern __shared__ char sm[];
    const u32 sb = smem_u32(sm);

    const int bh = blockIdx.z;
    const int b = bh / NHEADS, h = bh % NHEADS;
    const float* Qb = Q + (size_t)b * SEQ * DMODEL + h * DK;
    const float* Kb = Km + (size_t)b * SEQ * DMODEL + h * DK;
    float* Sout = attn + (size_t)bh * SEQ * SEQ;
    float* rsb = rowsum + (size_t)bh * SEQ;

    const int block_row = blockIdx.y * 128;
    const int block_col = blockIdx.x * 128;
    const int tid = threadIdx.x;
    const int wid = tid >> 5, lane = tid & 31;
    const int wm = wid & 3, wn = wid >> 2;

#pragma unroll
    for (int it = 0; it < 8; it++) {
        const int fid = tid + it * 256;
        const int row = fid >> 4, c4 = (fid & 15) * 4;
        const u32 boff = (u32)(row * TST + c4) * 2;

        float4 q = *(const float4*)&Qb[(size_t)(block_row + row) * DMODEL + c4];
        __nv_bfloat16 h0, l0, h1, l1, h2, l2, h3, l3;
        split_f(q.x, h0, l0); split_f(q.y, h1, l1);
        split_f(q.z, h2, l2); split_f(q.w, h3, l3);
        *(u32*)(sm + SC_QH + boff)     = pack_bf2(h0, h1);
        *(u32*)(sm + SC_QH + boff + 4) = pack_bf2(h2, h3);
        *(u32*)(sm + SC_QL + boff)     = pack_bf2(l0, l1);
        *(u32*)(sm + SC_QL + boff + 4) = pack_bf2(l2, l3);

        float4 k = *(const float4*)&Kb[(size_t)(block_col + row) * DMODEL + c4];
        split_f(k.x, h0, l0); split_f(k.y, h1, l1);
        split_f(k.z, h2, l2); split_f(k.w, h3, l3);
        *(u32*)(sm + SC_KH + boff)     = pack_bf2(h0, h1);
        *(u32*)(sm + SC_KH + boff + 4) = pack_bf2(h2, h3);
        *(u32*)(sm + SC_KL + boff)     = pack_bf2(l0, l1);
        *(u32*)(sm + SC_KL + boff + 4) = pack_bf2(l2, l3);
    }
    __syncthreads();

    float acc[2][8][4];
#pragma unroll
    for (int mi = 0; mi < 2; mi++)
#pragma unroll
        for (int ni = 0; ni < 8; ni++)
#pragma unroll
            for (int j = 0; j < 4; j++) acc[mi][ni][j] = 0.0f;

    const int lrow = lane & 15, lhalf = lane >> 4;

#pragma unroll
    for (int ks = 0; ks < 4; ks++) {
        const u32 kcol = (u32)(ks * 16 + lhalf * 8);
        u32 ah[2][4], al[2][4];
#pragma unroll
        for (int mi = 0; mi < 2; mi++) {
            const u32 ro = (u32)((wm * 32 + mi * 16 + lrow) * TST);
            u32 ad = sb + SC_QH + (ro + kcol) * 2;
            LDSM_X4(ah[mi][0], ah[mi][1], ah[mi][2], ah[mi][3], ad);
            ad = sb + SC_QL + (ro + kcol) * 2;
            LDSM_X4(al[mi][0], al[mi][1], al[mi][2], al[mi][3], ad);
        }
        u32 bhf[4][4], blf[4][4];
#pragma unroll
        for (int np = 0; np < 4; np++) {
            const u32 ro = (u32)((wn * 64 + np * 16 + lrow) * TST);
            u32 bd = sb + SC_KH + (ro + kcol) * 2;
            LDSM_X4(bhf[np][0], bhf[np][1], bhf[np][2], bhf[np][3], bd);
            bd = sb + SC_KL + (ro + kcol) * 2;
            LDSM_X4(blf[np][0], blf[np][1], blf[np][2], blf[np][3], bd);
        }
#pragma unroll
        for (int mi = 0; mi < 2; mi++)
#pragma unroll
            for (int np = 0; np < 4; np++)
#pragma unroll
                for (int sub = 0; sub < 2; sub++) {
                    const int ni = np * 2 + sub;
                    mma_bf16(acc[mi][ni], ah[mi], bhf[np][sub], bhf[np][sub + 2]);
                    mma_bf16(acc[mi][ni], ah[mi], blf[np][sub], blf[np][sub + 2]);
                    mma_bf16(acc[mi][ni], al[mi], bhf[np][sub], bhf[np][sub + 2]);
                }
    }

    // Epilogue: exp(s/8), stores + per-row partial-sum atomics
    const float scale = 0.125f;
    const int rbase = block_row + wm * 32 + (lane >> 2);
    const int cbase = block_col + wn * 64 + (lane & 3) * 2;
#pragma unroll
    for (int mi = 0; mi < 2; mi++)
#pragma unroll
        for (int half = 0; half < 2; half++) {
            const int r = rbase + mi * 16 + half * 8;
            float* rowp = Sout + (size_t)r * SEQ;
            float rsum = 0.0f;
#pragma unroll
            for (int ni = 0; ni < 8; ni++) {
                float2 e;
                e.x = __expf(scale * acc[mi][ni][half * 2]);
                e.y = __expf(scale * acc[mi][ni][half * 2 + 1]);
                rsum += e.x + e.y;
                *(float2*)&rowp[cbase + ni * 8] = e;
            }
            // quad reduce (lanes sharing this row differ in bits 0..1)
            rsum += __shfl_xor_sync(0xFFFFFFFFu, rsum, 1);
            rsum += __shfl_xor_sync(0xFFFFFFFFu, rsum, 2);
            if ((lane & 3) == 0) atomicAdd(&rsb[r], rsum);
        }
}

// ===========================================================================
// PV via HMMA. inv from global rowsum (no Phase-A pass). Per 64-k tile:
// P = E*inv (write back = final attn weights), split, HMMA accumulate O.
// ===========================================================================
#define PV_PH 0
#define PV_PL 18432
#define PV_VTH 36864
#define PV_VTL 46080
#define PV_INV 55296
#define PV_SMEM (55296 + 512)

__global__ __launch_bounds__(256) void pv_tc_kernel(
    float* __restrict__ attn, const float* __restrict__ V,
    float* __restrict__ AO, const float* __restrict__ rowsum)
{
    extern __shared__ char sm[];
    const u32 sb = smem_u32(sm);
    float* inv_s = (float*)(sm + PV_INV);

    const int bh = blockIdx.z;
    const int b = bh / NHEADS, h = bh % NHEADS;
    const int block_row = blockIdx.y * 128;
    float* Sbase = attn + (size_t)bh * SEQ * SEQ + (size_t)block_row * SEQ;
    const float* Vb = V + (size_t)b * SEQ * DMODEL + h * DK;
    float* Ob = AO + (size_t)(b * SEQ + block_row) * DMODEL + h * DK;
    const float* rsb = rowsum + (size_t)bh * SEQ + block_row;

    const int tid = threadIdx.x;
    const int wid = tid >> 5, lane = tid & 31;
    const int wm = wid & 3, wn = wid >> 2;

    if (tid < 128) inv_s[tid] = 1.0f / rsb[tid];
    __syncthreads();

    float acc[2][4][4];
#pragma unroll
    for (int mi = 0; mi < 2; mi++)
#pragma unroll
        for (int ni = 0; ni < 4; ni++)
#pragma unroll
            for (int j = 0; j < 4; j++) acc[mi][ni][j] = 0.0f;

    const int lrow = lane & 15, lhalf = lane >> 4;

    for (int t = 0; t < 32; t++) {
        const int k0 = t * 64;

#pragma unroll
        for (int l = 0; l < 8; l++) {
            const int fid = tid + l * 256;
            const int row = fid >> 4, c4 = (fid & 15) * 4;
            float* sp = Sbase + (size_t)row * SEQ + k0 + c4;
            float4 e = *(const float4*)sp;
            const float inv = inv_s[row];
            e.x *= inv; e.y *= inv; e.z *= inv; e.w *= inv;
            *(float4*)sp = e;
            __nv_bfloat16 h0, l0, h1, l1, h2, l2, h3, l3;
            split_f(e.x, h0, l0); split_f(e.y, h1, l1);
            split_f(e.z, h2, l2); split_f(e.w, h3, l3);
            const u32 boff = (u32)(row * TST + c4) * 2;
            *(u32*)(sm + PV_PH + boff)     = pack_bf2(h0, h1);
            *(u32*)(sm + PV_PH + boff + 4) = pack_bf2(h2, h3);
            *(u32*)(sm + PV_PL + boff)     = pack_bf2(l0, l1);
            *(u32*)(sm + PV_PL + boff + 4) = pack_bf2(l2, l3);
        }
#pragma unroll
        for (int l = 0; l < 4; l++) {
            const int fid = tid + l * 256;
            const int kr = fid >> 4, n4 = (fid & 15) * 4;
            float4 v = *(const float4*)&Vb[(size_t)(k0 + kr) * DMODEL + n4];
            float vv[4] = {v.x, v.y, v.z, v.w};
#pragma unroll
            for (int e = 0; e < 4; e++) {
                __nv_bfloat16 hh, ll;
                split_f(vv[e], hh, ll);
                const u32 boff = (u32)((n4 + e) * TST + kr) * 2;
                *(__nv_bfloat16*)(sm + PV_VTH + boff) = hh;
                *(__nv_bfloat16*)(sm + PV_VTL + boff) = ll;
            }
        }
        __syncthreads();

#pragma unroll
        for (int ks = 0; ks < 4; ks++) {
            const u32 kcol = (u32)(ks * 16 + lhalf * 8);
            u32 ah[2][4], al[2][4];
#pragma unroll
            for (int mi = 0; mi < 2; mi++) {
                const u32 ro = (u32)((wm * 32 + mi * 16 + lrow) * TST);
                u32 ad = sb + PV_PH + (ro + kcol) * 2;
                LDSM_X4(ah[mi][0], ah[mi][1], ah[mi][2], ah[mi][3], ad);
                ad = sb + PV_PL + (ro + kcol) * 2;
                LDSM_X4(al[mi][0], al[mi][1], al[mi][2], al[mi][3], ad);
            }
            u32 bhf[2][4], blf[2][4];
#pragma unroll
            for (int np = 0; np < 2; np++) {
                const u32 ro = (u32)((wn * 32 + np * 16 + lrow) * TST);
                u32 bd = sb + PV_VTH + (ro + kcol) * 2;
                LDSM_X4(bhf[np][0], bhf[np][1], bhf[np][2], bhf[np][3], bd);
                bd = sb + PV_VTL + (ro + kcol) * 2;
                LDSM_X4(blf[np][0], blf[np][1], blf[np][2], blf[np][3], bd);
            }
#pragma unroll
            for (int mi = 0; mi < 2; mi++)
#pragma unroll
                for (int np = 0; np < 2; np++)
#pragma unroll
                    for (int sub = 0; sub < 2; sub++) {
                        const int ni = np * 2 + sub;
                        mma_bf16(acc[mi][ni], ah[mi], bhf[np][sub], bhf[np][sub + 2]);
                        mma_bf16(acc[mi][ni], ah[mi], blf[np][sub], blf[np][sub + 2]);
                        mma_bf16(acc[mi][ni], al[mi], bhf[np][sub], bhf[np][sub + 2]);
                    }
        }
        __syncthreads();
    }

    const int rbase = wm * 32 + (lane >> 2);
    const int cbase = wn * 32 + (lane & 3) * 2;
#pragma unroll
    for (int mi = 0; mi < 2; mi++)
#pragma unroll
        for (int half = 0; half < 2; half++) {
            const int r = rbase + mi * 16 + half * 8;
            float* orow = Ob + (size_t)r * DMODEL;
#pragma unroll
            for (int ni = 0; ni < 4; ni++) {
                float2 o;
                o.x = acc[mi][ni][half * 2];
                o.y = acc[mi][ni][half * 2 + 1];
                *(float2*)&orow[cbase + ni * 8] = o;
            }
        }
}

// ===========================================================================
extern "C" void kernel_launch(void* const* d_in, const int* in_sizes, int n_in,
                              void* d_out, int out_size)
{
    const float* query = (const float*)d_in[0];
    const float* key   = (const float*)d_in[1];
    const float* value = (const float*)d_in[2];
    const float* Wq = (const float*)d_in[3];
    const float* bq = (const float*)d_in[4];
    const float* Wk = (const float*)d_in[5];
    const float* bk = (const float*)d_in[6];
    const float* Wv = (const float*)d_in[7];
    const float* bv = (const float*)d_in[8];
    const float* Wo = (const float*)d_in[9];
    const float* bo = (const float*)d_in[10];

    float* out  = (float*)d_out;
    float* attn = out + (size_t)MTOK * DMODEL;

    float *Qp, *Kp, *Vp, *AOp, *rsp;
    cudaGetSymbolAddress((void**)&Qp,  g_Q);
    cudaGetSymbolAddress((void**)&Kp,  g_K);
    cudaGetSymbolAddress((void**)&Vp,  g_V);
    cudaGetSymbolAddress((void**)&AOp, g_AO);
    cudaGetSymbolAddress((void**)&rsp, g_rowsum);

    static bool attr_done = false;
    if (!attr_done) {
        cudaFuncSetAttribute(proj_tc_kernel,
            cudaFuncAttributeMaxDynamicSharedMemorySize, PJ_SMEM);
        cudaFuncSetAttribute(scores_tc_kernel,
            cudaFuncAttributeMaxDynamicSharedMemorySize, SC_SMEM);
        cudaFuncSetAttribute(pv_tc_kernel,
            cudaFuncAttributeMaxDynamicSharedMemorySize, PV_SMEM);
        attr_done = true;
    }

    init_rowsum_kernel<<<(ATTN_ROWS + 255) / 256, 256>>>(rsp);

    dim3 gproj(DMODEL / 128, MTOK / 128);  // (6, 64)
    proj_tc_kernel<<<gproj, 256, PJ_SMEM>>>(query, Wq, bq, Qp);
    proj_tc_kernel<<<gproj, 256, PJ_SMEM>>>(key,   Wk, bk, Kp);
    proj_tc_kernel<<<gproj, 256, PJ_SMEM>>>(value, Wv, bv, Vp);

    dim3 gscores(SEQ / 128, SEQ / 128, BATCH * NHEADS);  // (16, 16, 48)
    scores_tc_kernel<<<gscores, 256, SC_SMEM>>>(Qp, Kp, attn, rsp);

    dim3 gpv(1, SEQ / 128, BATCH * NHEADS);  // (1, 16, 48)
    pv_tc_kernel<<<gpv, 256, PV_SMEM>>>(attn, Vp, AOp, rsp);

    proj_tc_kernel<<<gproj, 256, PJ_SMEM>>>(AOp, Wo, bo, out);
}

// round 14
// speedup vs baseline: 1.8372x; 1.1927x over previous
#include <cuda_runtime.h>
#include <cuda_bf16.h>
#include <math.h>

#define BATCH 4
#define SEQ 2048
#define DMODEL 768
#define NHEADS 12
#define DK 64
#define MTOK (BATCH * SEQ)                 // 8192
#define ATTN_ROWS (BATCH * NHEADS * SEQ)   // 98304

typedef unsigned int u32;

// ---------------------------------------------------------------------------
// Persistent bf16 hi/lo interchange buffers (__device__ globals, no allocs)
// ---------------------------------------------------------------------------
__device__ __nv_bfloat16 g_Xh[3 * MTOK * DMODEL];   // split inputs q,k,v
__device__ __nv_bfloat16 g_Xl[3 * MTOK * DMODEL];
__device__ __nv_bfloat16 g_WTh[4 * DMODEL * DMODEL]; // split transposed weights
__device__ __nv_bfloat16 g_WTl[4 * DMODEL * DMODEL];
__device__ __nv_bfloat16 g_Qh[MTOK * DMODEL], g_Ql[MTOK * DMODEL];
__device__ __nv_bfloat16 g_Kh[MTOK * DMODEL], g_Kl[MTOK * DMODEL];
__device__ __nv_bfloat16 g_Vh[MTOK * DMODEL], g_Vl[MTOK * DMODEL];
__device__ __nv_bfloat16 g_AOh[MTOK * DMODEL], g_AOl[MTOK * DMODEL];
__device__ float g_rowsum[ATTN_ROWS];

__global__ void init_rowsum_kernel(float* rs) {
    int i = blockIdx.x * blockDim.x + threadIdx.x;
    if (i < ATTN_ROWS) rs[i] = 0.0f;
}

// ---------------------------------------------------------------------------
// helpers
// ---------------------------------------------------------------------------
__device__ __forceinline__ u32 smem_u32(const void* p) {
    u32 a;
    asm("{ .reg .u64 t; cvta.to.shared.u64 t, %1; cvt.u32.u64 %0, t; }"
        : "=r"(a) : "l"(p));
    return a;
}

#define LDSM_X4(r0, r1, r2, r3, addr)                                        \
    asm volatile("ldmatrix.sync.aligned.m8n8.x4.shared.b16 {%0,%1,%2,%3}, [%4];" \
        : "=r"(r0), "=r"(r1), "=r"(r2), "=r"(r3) : "r"(addr))

__device__ __forceinline__ void mma_bf16(float* c, const u32* a, u32 b0, u32 b1) {
    asm volatile(
        "mma.sync.aligned.m16n8k16.row.col.f32.bf16.bf16.f32 "
        "{%0,%1,%2,%3}, {%4,%5,%6,%7}, {%8,%9}, {%0,%1,%2,%3};"
        : "+f"(c[0]), "+f"(c[1]), "+f"(c[2]), "+f"(c[3])
        : "r"(a[0]), "r"(a[1]), "r"(a[2]), "r"(a[3]), "r"(b0), "r"(b1));
}

__device__ __forceinline__ u32 pack_bf2(__nv_bfloat16 a, __nv_bfloat16 b) {
    __nv_bfloat162 t; t.x = a; t.y = b;
    return *reinterpret_cast<u32*>(&t);
}
__device__ __forceinline__ void split_f(float x, __nv_bfloat16& h, __nv_bfloat16& l) {
    h = __float2bfloat16(x);
    l = __float2bfloat16(x - __bfloat162float(h));
}

// smem row stride for bf16 tiles (64 data + 8 pad): 144B rows
#define TST 72

// ---------------------------------------------------------------------------
// Prep: split fp32 tensor into hi/lo bf16 (vectorized)
// ---------------------------------------------------------------------------
__global__ __launch_bounds__(256) void split_input_kernel(
    const float* __restrict__ src, __nv_bfloat16* __restrict__ dh,
    __nv_bfloat16* __restrict__ dl, int n4)
{
    int i = blockIdx.x * blockDim.x + threadIdx.x;
    if (i >= n4) return;
    float4 v = ((const float4*)src)[i];
    __nv_bfloat16 h0, l0, h1, l1, h2, l2, h3, l3;
    split_f(v.x, h0, l0); split_f(v.y, h1, l1);
    split_f(v.z, h2, l2); split_f(v.w, h3, l3);
    ((u32*)dh)[i * 2]     = pack_bf2(h0, h1);
    ((u32*)dh)[i * 2 + 1] = pack_bf2(h2, h3);
    ((u32*)dl)[i * 2]     = pack_bf2(l0, l1);
    ((u32*)dl)[i * 2 + 1] = pack_bf2(l2, l3);
}

// Prep: W[K][N] fp32 -> WT[N][K] hi/lo bf16 (tiled transpose)
__global__ void split_weight_kernel(
    const float* __restrict__ W, __nv_bfloat16* __restrict__ WTh,
    __nv_bfloat16* __restrict__ WTl)
{
    __shared__ float t[32][33];
    const int bn = blockIdx.x * 32, bk = blockIdx.y * 32;
    const int tx = threadIdx.x, ty4 = threadIdx.y * 4;
#pragma unroll
    for (int i = 0; i < 4; i++)
        t[ty4 + i][tx] = W[(size_t)(bk + ty4 + i) * DMODEL + bn + tx];
    __syncthreads();
#pragma unroll
    for (int i = 0; i < 4; i++) {
        float v = t[tx][ty4 + i];   // = W[bk+tx][bn+ty4+i]
        __nv_bfloat16 h, l;
        split_f(v, h, l);
        WTh[(size_t)(bn + ty4 + i) * DMODEL + bk + tx] = h;
        WTl[(size_t)(bn + ty4 + i) * DMODEL + bk + tx] = l;
    }
}

// ===========================================================================
// Projection GEMM via HMMA, bf16 hi/lo in, fp32 or hi/lo out.
// C[M,N] = A[M,K] @ W[K,N] + bias.  Block 128x128, k-tiles of 64.
// Load stage = pure u32 copies (no split math).
// ===========================================================================
#define PJ_AH 0
#define PJ_AL 18432
#define PJ_WH 36864
#define PJ_WL 55296
#define PJ_SMEM 73728

template <bool OUT_FP32>
__global__ __launch_bounds__(256) void proj_bf_kernel(
    const __nv_bfloat16* __restrict__ Ah, const __nv_bfloat16* __restrict__ Al,
    const __nv_bfloat16* __restrict__ WTh, const __nv_bfloat16* __restrict__ WTl,
    const float* __restrict__ bias, float* __restrict__ Cf,
    __nv_bfloat16* __restrict__ Ch, __nv_bfloat16* __restrict__ Cl)
{
    extern __shared__ char smm[];
    const u32 sb = smem_u32(smm);

    const int block_row = blockIdx.y * 128;
    const int block_col = blockIdx.x * 128;
    const int tid = threadIdx.x;
    const int wid = tid >> 5, lane = tid & 31;
    const int wm = wid & 3, wn = wid >> 2;
    const int lrow = lane & 15, lhalf = lane >> 4;

    float acc[2][8][4];
#pragma unroll
    for (int mi = 0; mi < 2; mi++)
#pragma unroll
        for (int ni = 0; ni < 8; ni++)
#pragma unroll
            for (int j = 0; j < 4; j++) acc[mi][ni][j] = 0.0f;

    for (int kt = 0; kt < DMODEL; kt += 64) {
        // copy A and W tiles (each 128 rows x 32 u32), coalesced
#pragma unroll
        for (int it = 0; it < 16; it++) {
            const int fid = tid + it * 256;
            const int row = fid >> 5, col = fid & 31;
            const u32 boff = (u32)(row * TST + col * 2) * 2;
            const size_t ao = (size_t)(block_row + row) * DMODEL + kt + col * 2;
            *(u32*)(smm + PJ_AH + boff) = *(const u32*)&Ah[ao];
            *(u32*)(smm + PJ_AL + boff) = *(const u32*)&Al[ao];
            const size_t wo = (size_t)(block_col + row) * DMODEL + kt + col * 2;
            *(u32*)(smm + PJ_WH + boff) = *(const u32*)&WTh[wo];
            *(u32*)(smm + PJ_WL + boff) = *(const u32*)&WTl[wo];
        }
        __syncthreads();

#pragma unroll
        for (int ks = 0; ks < 4; ks++) {
            const u32 kcol = (u32)(ks * 16 + lhalf * 8);
            u32 ah[2][4], al[2][4];
#pragma unroll
            for (int mi = 0; mi < 2; mi++) {
                const u32 ro = (u32)((wm * 32 + mi * 16 + lrow) * TST);
                u32 ad = sb + PJ_AH + (ro + kcol) * 2;
                LDSM_X4(ah[mi][0], ah[mi][1], ah[mi][2], ah[mi][3], ad);
                ad = sb + PJ_AL + (ro + kcol) * 2;
                LDSM_X4(al[mi][0], al[mi][1], al[mi][2], al[mi][3], ad);
            }
            u32 bhf[4][4], blf[4][4];
#pragma unroll
            for (int np = 0; np < 4; np++) {
                const u32 ro = (u32)((wn * 64 + np * 16 + lrow) * TST);
                u32 bd = sb + PJ_WH + (ro + kcol) * 2;
                LDSM_X4(bhf[np][0], bhf[np][1], bhf[np][2], bhf[np][3], bd);
                bd = sb + PJ_WL + (ro + kcol) * 2;
                LDSM_X4(blf[np][0], blf[np][1], blf[np][2], blf[np][3], bd);
            }
#pragma unroll
            for (int mi = 0; mi < 2; mi++)
#pragma unroll
                for (int np = 0; np < 4; np++)
#pragma unroll
                    for (int sub = 0; sub < 2; sub++) {
                        const int ni = np * 2 + sub;
                        mma_bf16(acc[mi][ni], ah[mi], bhf[np][sub], bhf[np][sub + 2]);
                        mma_bf16(acc[mi][ni], ah[mi], blf[np][sub], blf[np][sub + 2]);
                        mma_bf16(acc[mi][ni], al[mi], bhf[np][sub], bhf[np][sub + 2]);
                    }
        }
        __syncthreads();
    }

    const int rbase = block_row + wm * 32 + (lane >> 2);
    const int cbase = block_col + wn * 64 + (lane & 3) * 2;
#pragma unroll
    for (int mi = 0; mi < 2; mi++)
#pragma unroll
        for (int half = 0; half < 2; half++) {
            const int r = rbase + mi * 16 + half * 8;
#pragma unroll
            for (int ni = 0; ni < 8; ni++) {
                const int c = cbase + ni * 8;
                float ox = acc[mi][ni][half * 2]     + bias[c];
                float oy = acc[mi][ni][half * 2 + 1] + bias[c + 1];
                if (OUT_FP32) {
                    float2 o; o.x = ox; o.y = oy;
                    *(float2*)&Cf[(size_t)r * DMODEL + c] = o;
                } else {
                    __nv_bfloat16 hx, lx, hy, ly;
                    split_f(ox, hx, lx); split_f(oy, hy, ly);
                    *(u32*)&Ch[(size_t)r * DMODEL + c] = pack_bf2(hx, hy);
                    *(u32*)&Cl[(size_t)r * DMODEL + c] = pack_bf2(lx, ly);
                }
            }
        }
}

// ===========================================================================
// Scores via HMMA: E = exp(<Q,K>/8), + per-row sum atomics.
// Q/K arrive pre-split: load stage = pure u32 copies.
// ===========================================================================
#define SC_QH 0
#define SC_QL 18432
#define SC_KH 36864
#define SC_KL 55296
#define SC_SMEM 73728

__global__ __launch_bounds__(256) void scores_tc_kernel(
    const __nv_bfloat16* __restrict__ Qh, const __nv_bfloat16* __restrict__ Ql,
    const __nv_bfloat16* __restrict__ Kh, const __nv_bfloat16* __restrict__ Kl,
    float* __restrict__ attn, float* __restrict__ rowsum)
{
    extern __shared__ char smm[];
    const u32 sb = smem_u32(smm);

    const int bh = blockIdx.z;
    const int b = bh / NHEADS, h = bh % NHEADS;
    const size_t hb = (size_t)b * SEQ * DMODEL + h * DK;
    const __nv_bfloat16* Qbh = Qh + hb;
    const __nv_bfloat16* Qbl = Ql + hb;
    const __nv_bfloat16* Kbh = Kh + hb;
    const __nv_bfloat16* Kbl = Kl + hb;
    float* Sout = attn + (size_t)bh * SEQ * SEQ;
    float* rsb = rowsum + (size_t)bh * SEQ;

    const int block_row = blockIdx.y * 128;
    const int block_col = blockIdx.x * 128;
    const int tid = threadIdx.x;
    const int wid = tid >> 5, lane = tid & 31;
    const int wm = wid & 3, wn = wid >> 2;

    // copy Q/K hi/lo tiles (128 rows x 32 u32 each)
#pragma unroll
    for (int it = 0; it < 16; it++) {
        const int fid = tid + it * 256;
        const int row = fid >> 5, col = fid & 31;
        const u32 boff = (u32)(row * TST + col * 2) * 2;
        const size_t qo = (size_t)(block_row + row) * DMODEL + col * 2;
        *(u32*)(smm + SC_QH + boff) = *(const u32*)&Qbh[qo];
        *(u32*)(smm + SC_QL + boff) = *(const u32*)&Qbl[qo];
        const size_t ko = (size_t)(block_col + row) * DMODEL + col * 2;
        *(u32*)(smm + SC_KH + boff) = *(const u32*)&Kbh[ko];
        *(u32*)(smm + SC_KL + boff) = *(const u32*)&Kbl[ko];
    }
    __syncthreads();

    float acc[2][8][4];
#pragma unroll
    for (int mi = 0; mi < 2; mi++)
#pragma unroll
        for (int ni = 0; ni < 8; ni++)
#pragma unroll
            for (int j = 0; j < 4; j++) acc[mi][ni][j] = 0.0f;

    const int lrow = lane & 15, lhalf = lane >> 4;

#pragma unroll
    for (int ks = 0; ks < 4; ks++) {
        const u32 kcol = (u32)(ks * 16 + lhalf * 8);
        u32 ah[2][4], al[2][4];
#pragma unroll
        for (int mi = 0; mi < 2; mi++) {
            const u32 ro = (u32)((wm * 32 + mi * 16 + lrow) * TST);
            u32 ad = sb + SC_QH + (ro + kcol) * 2;
            LDSM_X4(ah[mi][0], ah[mi][1], ah[mi][2], ah[mi][3], ad);
            ad = sb + SC_QL + (ro + kcol) * 2;
            LDSM_X4(al[mi][0], al[mi][1], al[mi][2], al[mi][3], ad);
        }
        u32 bhf[4][4], blf[4][4];
#pragma unroll
        for (int np = 0; np < 4; np++) {
            const u32 ro = (u32)((wn * 64 + np * 16 + lrow) * TST);
            u32 bd = sb + SC_KH + (ro + kcol) * 2;
            LDSM_X4(bhf[np][0], bhf[np][1], bhf[np][2], bhf[np][3], bd);
            bd = sb + SC_KL + (ro + kcol) * 2;
            LDSM_X4(blf[np][0], blf[np][1], blf[np][2], blf[np][3], bd);
        }
#pragma unroll
        for (int mi = 0; mi < 2; mi++)
#pragma unroll
            for (int np = 0; np < 4; np++)
#pragma unroll
                for (int sub = 0; sub < 2; sub++) {
                    const int ni = np * 2 + sub;
                    mma_bf16(acc[mi][ni], ah[mi], bhf[np][sub], bhf[np][sub + 2]);
                    mma_bf16(acc[mi][ni], ah[mi], blf[np][sub], blf[np][sub + 2]);
                    mma_bf16(acc[mi][ni], al[mi], bhf[np][sub], bhf[np][sub + 2]);
                }
    }

    const float scale = 0.125f;
    const int rbase = block_row + wm * 32 + (lane >> 2);
    const int cbase = block_col + wn * 64 + (lane & 3) * 2;
#pragma unroll
    for (int mi = 0; mi < 2; mi++)
#pragma unroll
        for (int half = 0; half < 2; half++) {
            const int r = rbase + mi * 16 + half * 8;
            float* rowp = Sout + (size_t)r * SEQ;
            float rsum = 0.0f;
#pragma unroll
            for (int ni = 0; ni < 8; ni++) {
                float2 e;
                e.x = __expf(scale * acc[mi][ni][half * 2]);
                e.y = __expf(scale * acc[mi][ni][half * 2 + 1]);
                rsum += e.x + e.y;
                *(float2*)&rowp[cbase + ni * 8] = e;
            }
            rsum += __shfl_xor_sync(0xFFFFFFFFu, rsum, 1);
            rsum += __shfl_xor_sync(0xFFFFFFFFu, rsum, 2);
            if ((lane & 3) == 0) atomicAdd(&rsb[r], rsum);
        }
}

// ===========================================================================
// PV via HMMA. inv from global rowsum. P split in-kernel (necessary);
// V arrives pre-split (u32 loads, bf16 transpose stores);
// AO emitted as hi/lo bf16 for the final projection.
// ===========================================================================
#define PV_PH 0
#define PV_PL 18432
#define PV_VTH 36864
#define PV_VTL 46080
#define PV_INV 55296
#define PV_SMEM (55296 + 512)

__global__ __launch_bounds__(256) void pv_tc_kernel(
    float* __restrict__ attn,
    const __nv_bfloat16* __restrict__ Vh, const __nv_bfloat16* __restrict__ Vl,
    __nv_bfloat16* __restrict__ AOh, __nv_bfloat16* __restrict__ AOl,
    const float* __restrict__ rowsum)
{
    extern __shared__ char smm[];
    const u32 sb = smem_u32(smm);
    float* inv_s = (float*)(smm + PV_INV);

    const int bh = blockIdx.z;
    const int b = bh / NHEADS, h = bh % NHEADS;
    const int block_row = blockIdx.y * 128;
    float* Sbase = attn + (size_t)bh * SEQ * SEQ + (size_t)block_row * SEQ;
    const size_t hb = (size_t)b * SEQ * DMODEL + h * DK;
    const __nv_bfloat16* Vbh = Vh + hb;
    const __nv_bfloat16* Vbl = Vl + hb;
    const size_t ob = (size_t)(b * SEQ + block_row) * DMODEL + h * DK;
    __nv_bfloat16* Obh = AOh + ob;
    __nv_bfloat16* Obl = AOl + ob;
    const float* rsb = rowsum + (size_t)bh * SEQ + block_row;

    const int tid = threadIdx.x;
    const int wid = tid >> 5, lane = tid & 31;
    const int wm = wid & 3, wn = wid >> 2;

    if (tid < 128) inv_s[tid] = 1.0f / rsb[tid];
    __syncthreads();

    float acc[2][4][4];
#pragma unroll
    for (int mi = 0; mi < 2; mi++)
#pragma unroll
        for (int ni = 0; ni < 4; ni++)
#pragma unroll
            for (int j = 0; j < 4; j++) acc[mi][ni][j] = 0.0f;

    const int lrow = lane & 15, lhalf = lane >> 4;

    for (int t = 0; t < 32; t++) {
        const int k0 = t * 64;

        // P tile: normalize E, write back final attn weights, split to smem
#pragma unroll
        for (int l = 0; l < 8; l++) {
            const int fid = tid + l * 256;
            const int row = fid >> 4, c4 = (fid & 15) * 4;
            float* sp = Sbase + (size_t)row * SEQ + k0 + c4;
            float4 e = *(const float4*)sp;
            const float inv = inv_s[row];
            e.x *= inv; e.y *= inv; e.z *= inv; e.w *= inv;
            *(float4*)sp = e;
            __nv_bfloat16 h0, l0, h1, l1, h2, l2, h3, l3;
            split_f(e.x, h0, l0); split_f(e.y, h1, l1);
            split_f(e.z, h2, l2); split_f(e.w, h3, l3);
            const u32 boff = (u32)(row * TST + c4) * 2;
            *(u32*)(smm + PV_PH + boff)     = pack_bf2(h0, h1);
            *(u32*)(smm + PV_PH + boff + 4) = pack_bf2(h2, h3);
            *(u32*)(smm + PV_PL + boff)     = pack_bf2(l0, l1);
            *(u32*)(smm + PV_PL + boff + 4) = pack_bf2(l2, l3);
        }
        // V tile [64 k][64 n] (pre-split) -> transposed [n][k] smem
#pragma unroll
        for (int l = 0; l < 8; l++) {
            const int fid = tid + l * 256;
            const int kr = fid >> 5, n2 = (fid & 31) * 2;
            const size_t vo = (size_t)(k0 + kr) * DMODEL + n2;
            u32 hv = *(const u32*)&Vbh[vo];
            u32 lv = *(const u32*)&Vbl[vo];
            __nv_bfloat162 h2v = *reinterpret_cast<__nv_bfloat162*>(&hv);
            __nv_bfloat162 l2v = *reinterpret_cast<__nv_bfloat162*>(&lv);
            const u32 b0 = (u32)(n2 * TST + kr) * 2;
            const u32 b1 = (u32)((n2 + 1) * TST + kr) * 2;
            *(__nv_bfloat16*)(smm + PV_VTH + b0) = h2v.x;
            *(__nv_bfloat16*)(smm + PV_VTH + b1) = h2v.y;
            *(__nv_bfloat16*)(smm + PV_VTL + b0) = l2v.x;
            *(__nv_bfloat16*)(smm + PV_VTL + b1) = l2v.y;
        }
        __syncthreads();

#pragma unroll
        for (int ks = 0; ks < 4; ks++) {
            const u32 kcol = (u32)(ks * 16 + lhalf * 8);
            u32 ah[2][4], al[2][4];
#pragma unroll
            for (int mi = 0; mi < 2; mi++) {
                const u32 ro = (u32)((wm * 32 + mi * 16 + lrow) * TST);
                u32 ad = sb + PV_PH + (ro + kcol) * 2;
                LDSM_X4(ah[mi][0], ah[mi][1], ah[mi][2], ah[mi][3], ad);
                ad = sb + PV_PL + (ro + kcol) * 2;
                LDSM_X4(al[mi][0], al[mi][1], al[mi][2], al[mi][3], ad);
            }
            u32 bhf[2][4], blf[2][4];
#pragma unroll
            for (int np = 0; np < 2; np++) {
                const u32 ro = (u32)((wn * 32 + np * 16 + lrow) * TST);
                u32 bd = sb + PV_VTH + (ro + kcol) * 2;
                LDSM_X4(bhf[np][0], bhf[np][1], bhf[np][2], bhf[np][3], bd);
                bd = sb + PV_VTL + (ro + kcol) * 2;
                LDSM_X4(blf[np][0], blf[np][1], blf[np][2], blf[np][3], bd);
            }
#pragma unroll
            for (int mi = 0; mi < 2; mi++)
#pragma unroll
                for (int np = 0; np < 2; np++)
#pragma unroll
                    for (int sub = 0; sub < 2; sub++) {
                        const int ni = np * 2 + sub;
                        mma_bf16(acc[mi][ni], ah[mi], bhf[np][sub], bhf[np][sub + 2]);
                        mma_bf16(acc[mi][ni], ah[mi], blf[np][sub], blf[np][sub + 2]);
                        mma_bf16(acc[mi][ni], al[mi], bhf[np][sub], bhf[np][sub + 2]);
                    }
        }
        __syncthreads();
    }

    // Epilogue: emit AO as hi/lo bf16
    const int rbase = wm * 32 + (lane >> 2);
    const int cbase = wn * 32 + (lane & 3) * 2;
#pragma unroll
    for (int mi = 0; mi < 2; mi++)
#pragma unroll
        for (int half = 0; half < 2; half++) {
            const int r = rbase + mi * 16 + half * 8;
#pragma unroll
            for (int ni = 0; ni < 4; ni++) {
                const int c = cbase + ni * 8;
                float ox = acc[mi][ni][half * 2];
                float oy = acc[mi][ni][half * 2 + 1];
                __nv_bfloat16 hx, lx, hy, ly;
                split_f(ox, hx, lx); split_f(oy, hy, ly);
                *(u32*)&Obh[(size_t)r * DMODEL + c] = pack_bf2(hx, hy);
                *(u32*)&Obl[(size_t)r * DMODEL + c] = pack_bf2(lx, ly);
            }
        }
}

// ===========================================================================
extern "C" void kernel_launch(void* const* d_in, const int* in_sizes, int n_in,
                              void* d_out, int out_size)
{
    const float* query = (const float*)d_in[0];
    const float* key   = (const float*)d_in[1];
    const float* value = (const float*)d_in[2];
    const float* Wq = (const float*)d_in[3];
    const float* bq = (const float*)d_in[4];
    const float* Wk = (const float*)d_in[5];
    const float* bk = (const float*)d_in[6];
    const float* Wv = (const float*)d_in[7];
    const float* bv = (const float*)d_in[8];
    const float* Wo = (const float*)d_in[9];
    const float* bo = (const float*)d_in[10];

    float* out  = (float*)d_out;
    float* attn = out + (size_t)MTOK * DMODEL;

    __nv_bfloat16 *Xh, *Xl, *WTh, *WTl;
    __nv_bfloat16 *Qh, *Ql, *Kh, *Kl, *Vh, *Vl, *AOh, *AOl;
    float* rsp;
    cudaGetSymbolAddress((void**)&Xh,  g_Xh);
    cudaGetSymbolAddress((void**)&Xl,  g_Xl);
    cudaGetSymbolAddress((void**)&WTh, g_WTh);
    cudaGetSymbolAddress((void**)&WTl, g_WTl);
    cudaGetSymbolAddress((void**)&Qh,  g_Qh);
    cudaGetSymbolAddress((void**)&Ql,  g_Ql);
    cudaGetSymbolAddress((void**)&Kh,  g_Kh);
    cudaGetSymbolAddress((void**)&Kl,  g_Kl);
    cudaGetSymbolAddress((void**)&Vh,  g_Vh);
    cudaGetSymbolAddress((void**)&Vl,  g_Vl);
    cudaGetSymbolAddress((void**)&AOh, g_AOh);
    cudaGetSymbolAddress((void**)&AOl, g_AOl);
    cudaGetSymbolAddress((void**)&rsp, g_rowsum);

    static bool attr_done = false;
    if (!attr_done) {
        cudaFuncSetAttribute(proj_bf_kernel<true>,
            cudaFuncAttributeMaxDynamicSharedMemorySize, PJ_SMEM);
        cudaFuncSetAttribute(proj_bf_kernel<false>,
            cudaFuncAttributeMaxDynamicSharedMemorySize, PJ_SMEM);
        cudaFuncSetAttribute(scores_tc_kernel,
            cudaFuncAttributeMaxDynamicSharedMemorySize, SC_SMEM);
        cudaFuncSetAttribute(pv_tc_kernel,
            cudaFuncAttributeMaxDynamicSharedMemorySize, PV_SMEM);
        attr_done = true;
    }

    init_rowsum_kernel<<<(ATTN_ROWS + 255) / 256, 256>>>(rsp);

    // Prep: split inputs + weights
    const int n4 = MTOK * DMODEL / 4;
    const size_t TD = (size_t)MTOK * DMODEL;
    const size_t WD = (size_t)DMODEL * DMODEL;
    split_input_kernel<<<(n4 + 255) / 256, 256>>>(query, Xh,          Xl,          n4);
    split_input_kernel<<<(n4 + 255) / 256, 256>>>(key,   Xh + TD,     Xl + TD,     n4);
    split_input_kernel<<<(n4 + 255) / 256, 256>>>(value, Xh + 2 * TD, Xl + 2 * TD, n4);
    dim3 wgrid(DMODEL / 32, DMODEL / 32), wblk(32, 8);
    split_weight_kernel<<<wgrid, wblk>>>(Wq, WTh,          WTl);
    split_weight_kernel<<<wgrid, wblk>>>(Wk, WTh + WD,     WTl + WD);
    split_weight_kernel<<<wgrid, wblk>>>(Wv, WTh + 2 * WD, WTl + 2 * WD);
    split_weight_kernel<<<wgrid, wblk>>>(Wo, WTh + 3 * WD, WTl + 3 * WD);

    dim3 gproj(DMODEL / 128, MTOK / 128);  // (6, 64)
    proj_bf_kernel<false><<<gproj, 256, PJ_SMEM>>>(
        Xh,          Xl,          WTh,          WTl,          bq, nullptr, Qh, Ql);
    proj_bf_kernel<false><<<gproj, 256, PJ_SMEM>>>(
        Xh + TD,     Xl + TD,     WTh + WD,     WTl + WD,     bk, nullptr, Kh, Kl);
    proj_bf_kernel<false><<<gproj, 256, PJ_SMEM>>>(
        Xh + 2 * TD, Xl + 2 * TD, WTh + 2 * WD, WTl + 2 * WD, bv, nullptr, Vh, Vl);

    dim3 gscores(SEQ / 128, SEQ / 128, BATCH * NHEADS);  // (16, 16, 48)
    scores_tc_kernel<<<gscores, 256, SC_SMEM>>>(Qh, Ql, Kh, Kl, attn, rsp);

    dim3 gpv(1, SEQ / 128, BATCH * NHEADS);  // (1, 16, 48)
    pv_tc_kernel<<<gpv, 256, PV_SMEM>>>(attn, Vh, Vl, AOh, AOl, rsp);

    proj_bf_kernel<true><<<gproj, 256, PJ_SMEM>>>(
        AOh, AOl, WTh + 3 * WD, WTl + 3 * WD, bo, out, nullptr, nullptr);
}

// round 16
// speedup vs baseline: 2.2324x; 1.2151x over previous
#include <cuda_runtime.h>
#include <cuda_bf16.h>
#include <math.h>

#define BATCH 4
#define SEQ 2048
#define DMODEL 768
#define NHEADS 12
#define DK 64
#define MTOK (BATCH * SEQ)                 // 8192
#define ATTN_ROWS (BATCH * NHEADS * SEQ)   // 98304

typedef unsigned int u32;

// ---------------------------------------------------------------------------
// Persistent bf16 hi/lo interchange buffers (__device__ globals, no allocs)
// ---------------------------------------------------------------------------
__device__ __nv_bfloat16 g_Xh[3 * MTOK * DMODEL];
__device__ __nv_bfloat16 g_Xl[3 * MTOK * DMODEL];
__device__ __nv_bfloat16 g_WTh[4 * DMODEL * DMODEL];
__device__ __nv_bfloat16 g_WTl[4 * DMODEL * DMODEL];
__device__ __nv_bfloat16 g_Qh[MTOK * DMODEL], g_Ql[MTOK * DMODEL];
__device__ __nv_bfloat16 g_Kh[MTOK * DMODEL], g_Kl[MTOK * DMODEL];
__device__ __nv_bfloat16 g_Vh[MTOK * DMODEL], g_Vl[MTOK * DMODEL];
__device__ __nv_bfloat16 g_VTh[MTOK * DMODEL], g_VTl[MTOK * DMODEL]; // [bh][n][k]
__device__ __nv_bfloat16 g_AOh[MTOK * DMODEL], g_AOl[MTOK * DMODEL];
__device__ float g_rowsum[ATTN_ROWS];

__global__ void init_rowsum_kernel(float* rs) {
    int i = blockIdx.x * blockDim.x + threadIdx.x;
    if (i < ATTN_ROWS) rs[i] = 0.0f;
}

// ---------------------------------------------------------------------------
// helpers
// ---------------------------------------------------------------------------
__device__ __forceinline__ u32 smem_u32(const void* p) {
    u32 a;
    asm("{ .reg .u64 t; cvta.to.shared.u64 t, %1; cvt.u32.u64 %0, t; }"
        : "=r"(a) : "l"(p));
    return a;
}

#define LDSM_X4(r0, r1, r2, r3, addr)                                        \
    asm volatile("ldmatrix.sync.aligned.m8n8.x4.shared.b16 {%0,%1,%2,%3}, [%4];" \
        : "=r"(r0), "=r"(r1), "=r"(r2), "=r"(r3) : "r"(addr))

#define CP16(dst, src)                                                       \
    asm volatile("cp.async.cg.shared.global [%0], [%1], 16;"                 \
        :: "r"(dst), "l"(src))
#define CP_COMMIT() asm volatile("cp.async.commit_group;" ::: "memory")
#define CP_WAIT0()  asm volatile("cp.async.wait_group 0;" ::: "memory")

__device__ __forceinline__ void mma_bf16(float* c, const u32* a, u32 b0, u32 b1) {
    asm volatile(
        "mma.sync.aligned.m16n8k16.row.col.f32.bf16.bf16.f32 "
        "{%0,%1,%2,%3}, {%4,%5,%6,%7}, {%8,%9}, {%0,%1,%2,%3};"
        : "+f"(c[0]), "+f"(c[1]), "+f"(c[2]), "+f"(c[3])
        : "r"(a[0]), "r"(a[1]), "r"(a[2]), "r"(a[3]), "r"(b0), "r"(b1));
}

__device__ __forceinline__ u32 pack_bf2(__nv_bfloat16 a, __nv_bfloat16 b) {
    __nv_bfloat162 t; t.x = a; t.y = b;
    return *reinterpret_cast<u32*>(&t);
}
__device__ __forceinline__ void split_f(float x, __nv_bfloat16& h, __nv_bfloat16& l) {
    h = __float2bfloat16(x);
    l = __float2bfloat16(x - __bfloat162float(h));
}

#define TST 72   // bf16 row stride (64 data + 8 pad) = 144B

// ---------------------------------------------------------------------------
// Prep kernels
// ---------------------------------------------------------------------------
__global__ __launch_bounds__(256) void split_input_kernel(
    const float* __restrict__ src, __nv_bfloat16* __restrict__ dh,
    __nv_bfloat16* __restrict__ dl, int n4)
{
    int i = blockIdx.x * blockDim.x + threadIdx.x;
    if (i >= n4) return;
    float4 v = ((const float4*)src)[i];
    __nv_bfloat16 h0, l0, h1, l1, h2, l2, h3, l3;
    split_f(v.x, h0, l0); split_f(v.y, h1, l1);
    split_f(v.z, h2, l2); split_f(v.w, h3, l3);
    ((u32*)dh)[i * 2]     = pack_bf2(h0, h1);
    ((u32*)dh)[i * 2 + 1] = pack_bf2(h2, h3);
    ((u32*)dl)[i * 2]     = pack_bf2(l0, l1);
    ((u32*)dl)[i * 2 + 1] = pack_bf2(l2, l3);
}

__global__ void split_weight_kernel(
    const float* __restrict__ W, __nv_bfloat16* __restrict__ WTh,
    __nv_bfloat16* __restrict__ WTl)
{
    __shared__ float t[32][33];
    const int bn = blockIdx.x * 32, bk = blockIdx.y * 32;
    const int tx = threadIdx.x, ty4 = threadIdx.y * 4;
#pragma unroll
    for (int i = 0; i < 4; i++)
        t[ty4 + i][tx] = W[(size_t)(bk + ty4 + i) * DMODEL + bn + tx];
    __syncthreads();
#pragma unroll
    for (int i = 0; i < 4; i++) {
        float v = t[tx][ty4 + i];
        __nv_bfloat16 h, l;
        split_f(v, h, l);
        WTh[(size_t)(bn + ty4 + i) * DMODEL + bk + tx] = h;
        WTl[(size_t)(bn + ty4 + i) * DMODEL + bk + tx] = l;
    }
}

// V[token][head*DK+n] hi/lo -> VT[bh][n][k=token] hi/lo
__global__ void vtrans_kernel(
    const __nv_bfloat16* __restrict__ Vh, const __nv_bfloat16* __restrict__ Vl,
    __nv_bfloat16* __restrict__ VTh, __nv_bfloat16* __restrict__ VTl)
{
    __shared__ __nv_bfloat16 th[32][33];
    __shared__ __nv_bfloat16 tl[32][33];
    const int s0 = blockIdx.x * 32, n0 = blockIdx.y * 32;
    const int bh = blockIdx.z;
    const int b = bh / NHEADS, h = bh % NHEADS;
    const int tx = threadIdx.x, ty4 = threadIdx.y * 4;
#pragma unroll
    for (int i = 0; i < 4; i++) {
        const size_t src = (size_t)(b * SEQ + s0 + ty4 + i) * DMODEL + h * DK + n0 + tx;
        th[ty4 + i][tx] = Vh[src];
        tl[ty4 + i][tx] = Vl[src];
    }
    __syncthreads();
#pragma unroll
    for (int i = 0; i < 4; i++) {
        const size_t dst = (size_t)(bh * DK + n0 + ty4 + i) * SEQ + s0 + tx;
        VTh[dst] = th[tx][ty4 + i];
        VTl[dst] = tl[tx][ty4 + i];
    }
}

// ===========================================================================
// Projection GEMM via HMMA (unchanged)
// ===========================================================================
#define PJ_AH 0
#define PJ_AL 18432
#define PJ_WH 36864
#define PJ_WL 55296
#define PJ_SMEM 73728

template <bool OUT_FP32>
__global__ __launch_bounds__(256) void proj_bf_kernel(
    const __nv_bfloat16* __restrict__ Ah, const __nv_bfloat16* __restrict__ Al,
    const __nv_bfloat16* __restrict__ WTh, const __nv_bfloat16* __restrict__ WTl,
    const float* __restrict__ bias, float* __restrict__ Cf,
    __nv_bfloat16* __restrict__ Ch, __nv_bfloat16* __restrict__ Cl)
{
    extern __shared__ char smm[];
    const u32 sb = smem_u32(smm);

    const int block_row = blockIdx.y * 128;
    const int block_col = blockIdx.x * 128;
    const int tid = threadIdx.x;
    const int wid = tid >> 5, lane = tid & 31;
    const int wm = wid & 3, wn = wid >> 2;
    const int lrow = lane & 15, lhalf = lane >> 4;

    float acc[2][8][4];
#pragma unroll
    for (int mi = 0; mi < 2; mi++)
#pragma unroll
        for (int ni = 0; ni < 8; ni++)
#pragma unroll
            for (int j = 0; j < 4; j++) acc[mi][ni][j] = 0.0f;

    for (int kt = 0; kt < DMODEL; kt += 64) {
#pragma unroll
        for (int it = 0; it < 16; it++) {
            const int fid = tid + it * 256;
            const int row = fid >> 5, col = fid & 31;
            const u32 boff = (u32)(row * TST + col * 2) * 2;
            const size_t ao = (size_t)(block_row + row) * DMODEL + kt + col * 2;
            *(u32*)(smm + PJ_AH + boff) = *(const u32*)&Ah[ao];
            *(u32*)(smm + PJ_AL + boff) = *(const u32*)&Al[ao];
            const size_t wo = (size_t)(block_col + row) * DMODEL + kt + col * 2;
            *(u32*)(smm + PJ_WH + boff) = *(const u32*)&WTh[wo];
            *(u32*)(smm + PJ_WL + boff) = *(const u32*)&WTl[wo];
        }
        __syncthreads();

#pragma unroll
        for (int ks = 0; ks < 4; ks++) {
            const u32 kcol = (u32)(ks * 16 + lhalf * 8);
            u32 ah[2][4], al[2][4];
#pragma unroll
            for (int mi = 0; mi < 2; mi++) {
                const u32 ro = (u32)((wm * 32 + mi * 16 + lrow) * TST);
                u32 ad = sb + PJ_AH + (ro + kcol) * 2;
                LDSM_X4(ah[mi][0], ah[mi][1], ah[mi][2], ah[mi][3], ad);
                ad = sb + PJ_AL + (ro + kcol) * 2;
                LDSM_X4(al[mi][0], al[mi][1], al[mi][2], al[mi][3], ad);
            }
            u32 bhf[4][4], blf[4][4];
#pragma unroll
            for (int np = 0; np < 4; np++) {
                const u32 ro = (u32)((wn * 64 + np * 16 + lrow) * TST);
                u32 bd = sb + PJ_WH + (ro + kcol) * 2;
                LDSM_X4(bhf[np][0], bhf[np][1], bhf[np][2], bhf[np][3], bd);
                bd = sb + PJ_WL + (ro + kcol) * 2;
                LDSM_X4(blf[np][0], blf[np][1], blf[np][2], blf[np][3], bd);
            }
#pragma unroll
            for (int mi = 0; mi < 2; mi++)
#pragma unroll
                for (int np = 0; np < 4; np++)
#pragma unroll
                    for (int sub = 0; sub < 2; sub++) {
                        const int ni = np * 2 + sub;
                        mma_bf16(acc[mi][ni], ah[mi], bhf[np][sub], bhf[np][sub + 2]);
                        mma_bf16(acc[mi][ni], ah[mi], blf[np][sub], blf[np][sub + 2]);
                        mma_bf16(acc[mi][ni], al[mi], bhf[np][sub], bhf[np][sub + 2]);
                    }
        }
        __syncthreads();
    }

    const int rbase = block_row + wm * 32 + (lane >> 2);
    const int cbase = block_col + wn * 64 + (lane & 3) * 2;
#pragma unroll
    for (int mi = 0; mi < 2; mi++)
#pragma unroll
        for (int half = 0; half < 2; half++) {
            const int r = rbase + mi * 16 + half * 8;
#pragma unroll
            for (int ni = 0; ni < 8; ni++) {
                const int c = cbase + ni * 8;
                float ox = acc[mi][ni][half * 2]     + bias[c];
                float oy = acc[mi][ni][half * 2 + 1] + bias[c + 1];
                if (OUT_FP32) {
                    float2 o; o.x = ox; o.y = oy;
                    *(float2*)&Cf[(size_t)r * DMODEL + c] = o;
                } else {
                    __nv_bfloat16 hx, lx, hy, ly;
                    split_f(ox, hx, lx); split_f(oy, hy, ly);
                    *(u32*)&Ch[(size_t)r * DMODEL + c] = pack_bf2(hx, hy);
                    *(u32*)&Cl[(size_t)r * DMODEL + c] = pack_bf2(lx, ly);
                }
            }
        }
}

// ===========================================================================
// Scores via HMMA (unchanged)
// ===========================================================================
#define SC_QH 0
#define SC_QL 18432
#define SC_KH 36864
#define SC_KL 55296
#define SC_SMEM 73728

__global__ __launch_bounds__(256) void scores_tc_kernel(
    const __nv_bfloat16* __restrict__ Qh, const __nv_bfloat16* __restrict__ Ql,
    const __nv_bfloat16* __restrict__ Kh, const __nv_bfloat16* __restrict__ Kl,
    float* __restrict__ attn, float* __restrict__ rowsum)
{
    extern __shared__ char smm[];
    const u32 sb = smem_u32(smm);

    const int bh = blockIdx.z;
    const int b = bh / NHEADS, h = bh % NHEADS;
    const size_t hb = (size_t)b * SEQ * DMODEL + h * DK;
    const __nv_bfloat16* Qbh = Qh + hb;
    const __nv_bfloat16* Qbl = Ql + hb;
    const __nv_bfloat16* Kbh = Kh + hb;
    const __nv_bfloat16* Kbl = Kl + hb;
    float* Sout = attn + (size_t)bh * SEQ * SEQ;
    float* rsb = rowsum + (size_t)bh * SEQ;

    const int block_row = blockIdx.y * 128;
    const int block_col = blockIdx.x * 128;
    const int tid = threadIdx.x;
    const int wid = tid >> 5, lane = tid & 31;
    const int wm = wid & 3, wn = wid >> 2;

#pragma unroll
    for (int it = 0; it < 16; it++) {
        const int fid = tid + it * 256;
        const int row = fid >> 5, col = fid & 31;
        const u32 boff = (u32)(row * TST + col * 2) * 2;
        const size_t qo = (size_t)(block_row + row) * DMODEL + col * 2;
        *(u32*)(smm + SC_QH + boff) = *(const u32*)&Qbh[qo];
        *(u32*)(smm + SC_QL + boff) = *(const u32*)&Qbl[qo];
        const size_t ko = (size_t)(block_col + row) * DMODEL + col * 2;
        *(u32*)(smm + SC_KH + boff) = *(const u32*)&Kbh[ko];
        *(u32*)(smm + SC_KL + boff) = *(const u32*)&Kbl[ko];
    }
    __syncthreads();

    float acc[2][8][4];
#pragma unroll
    for (int mi = 0; mi < 2; mi++)
#pragma unroll
        for (int ni = 0; ni < 8; ni++)
#pragma unroll
            for (int j = 0; j < 4; j++) acc[mi][ni][j] = 0.0f;

    const int lrow = lane & 15, lhalf = lane >> 4;

#pragma unroll
    for (int ks = 0; ks < 4; ks++) {
        const u32 kcol = (u32)(ks * 16 + lhalf * 8);
        u32 ah[2][4], al[2][4];
#pragma unroll
        for (int mi = 0; mi < 2; mi++) {
            const u32 ro = (u32)((wm * 32 + mi * 16 + lrow) * TST);
            u32 ad = sb + SC_QH + (ro + kcol) * 2;
            LDSM_X4(ah[mi][0], ah[mi][1], ah[mi][2], ah[mi][3], ad);
            ad = sb + SC_QL + (ro + kcol) * 2;
            LDSM_X4(al[mi][0], al[mi][1], al[mi][2], al[mi][3], ad);
        }
        u32 bhf[4][4], blf[4][4];
#pragma unroll
        for (int np = 0; np < 4; np++) {
            const u32 ro = (u32)((wn * 64 + np * 16 + lrow) * TST);
            u32 bd = sb + SC_KH + (ro + kcol) * 2;
            LDSM_X4(bhf[np][0], bhf[np][1], bhf[np][2], bhf[np][3], bd);
            bd = sb + SC_KL + (ro + kcol) * 2;
            LDSM_X4(blf[np][0], blf[np][1], blf[np][2], blf[np][3], bd);
        }
#pragma unroll
        for (int mi = 0; mi < 2; mi++)
#pragma unroll
            for (int np = 0; np < 4; np++)
#pragma unroll
                for (int sub = 0; sub < 2; sub++) {
                    const int ni = np * 2 + sub;
                    mma_bf16(acc[mi][ni], ah[mi], bhf[np][sub], bhf[np][sub + 2]);
                    mma_bf16(acc[mi][ni], ah[mi], blf[np][sub], blf[np][sub + 2]);
                    mma_bf16(acc[mi][ni], al[mi], bhf[np][sub], bhf[np][sub + 2]);
                }
    }

    const float scale = 0.125f;
    const int rbase = block_row + wm * 32 + (lane >> 2);
    const int cbase = block_col + wn * 64 + (lane & 3) * 2;
#pragma unroll
    for (int mi = 0; mi < 2; mi++)
#pragma unroll
        for (int half = 0; half < 2; half++) {
            const int r = rbase + mi * 16 + half * 8;
            float* rowp = Sout + (size_t)r * SEQ;
            float rsum = 0.0f;
#pragma unroll
            for (int ni = 0; ni < 8; ni++) {
                float2 e;
                e.x = __expf(scale * acc[mi][ni][half * 2]);
                e.y = __expf(scale * acc[mi][ni][half * 2 + 1]);
                rsum += e.x + e.y;
                *(float2*)&rowp[cbase + ni * 8] = e;
            }
            rsum += __shfl_xor_sync(0xFFFFFFFFu, rsum, 1);
            rsum += __shfl_xor_sync(0xFFFFFFFFu, rsum, 2);
            if ((lane & 3) == 0) atomicAdd(&rsb[r], rsum);
        }
}

// ===========================================================================
// PV via HMMA with cp.async 2-stage pipeline (FIXED smem map).
// Layout (bytes):
//   PH    [0,      18432)   P hi tile [128][TST]
//   PL    [18432,  36864)   P lo tile
//   VTH0  [36864,  46080)   VT hi, stage 0 [64][TST]
//   VTL0  [46080,  55296)
//   VTH1  [55296,  64512)
//   VTL1  [64512,  73728)
//   ES0   [73728,  106496)  E fp32 tile [128][64] = 32768 B
//   ES1   [106496, 139264)
//   INV   [139264, 139776)
// ===========================================================================
#define PV_PH    0
#define PV_PL    18432
#define PV_VTH0  36864
#define PV_VTL0  46080
#define PV_VTH1  55296
#define PV_VTL1  64512
#define PV_ES0   73728
#define PV_ES1   106496
#define PV_INV   139264
#define PV_SMEM  139776

__global__ __launch_bounds__(256) void pv_tc_kernel(
    float* __restrict__ attn,
    const __nv_bfloat16* __restrict__ VTh, const __nv_bfloat16* __restrict__ VTl,
    __nv_bfloat16* __restrict__ AOh, __nv_bfloat16* __restrict__ AOl,
    const float* __restrict__ rowsum)
{
    extern __shared__ char smm[];
    const u32 sb = smem_u32(smm);
    float* inv_s = (float*)(smm + PV_INV);

    const int bh = blockIdx.z;
    const int b = bh / NHEADS, h = bh % NHEADS;
    const int block_row = blockIdx.y * 128;
    float* Sbase = attn + (size_t)bh * SEQ * SEQ + (size_t)block_row * SEQ;
    const __nv_bfloat16* VTgh = VTh + (size_t)bh * DK * SEQ;
    const __nv_bfloat16* VTgl = VTl + (size_t)bh * DK * SEQ;
    const size_t ob = (size_t)(b * SEQ + block_row) * DMODEL + h * DK;
    __nv_bfloat16* Obh = AOh + ob;
    __nv_bfloat16* Obl = AOl + ob;
    const float* rsb = rowsum + (size_t)bh * SEQ + block_row;

    const int tid = threadIdx.x;
    const int wid = tid >> 5, lane = tid & 31;
    const int wm = wid & 3, wn = wid >> 2;

    if (tid < 128) inv_s[tid] = 1.0f / rsb[tid];

    const u32 es_off[2]  = {PV_ES0, PV_ES1};
    const u32 vth_off[2] = {PV_VTH0, PV_VTH1};
    const u32 vtl_off[2] = {PV_VTL0, PV_VTL1};

    // issue cp.async for k-tile t into buffer buf
    auto issue_tile = [&](int t, int buf) {
        const int k0 = t * 64;
        // E tile: 128 rows x 64 fp32 = 2048 x 16B chunks (32768 B)
#pragma unroll
        for (int i = 0; i < 8; i++) {
            const int c = tid + i * 256;
            const int row = c >> 4, pos = c & 15;
            const u32 dst = sb + es_off[buf] + (u32)(row * 256 + pos * 16);
            const char* src = (const char*)(Sbase + (size_t)row * SEQ + k0 + pos * 4);
            CP16(dst, src);
        }
        // VT tiles: 64 n-rows x 64 k bf16 = 512 x 16B chunks each (hi, lo)
#pragma unroll
        for (int i = 0; i < 4; i++) {
            int c = tid + i * 256;
            if (c < 512) {
                const int n = c >> 3, pos = c & 7;
                const u32 dst = sb + vth_off[buf] + (u32)(n * (TST * 2) + pos * 16);
                const char* src = (const char*)(VTgh + (size_t)n * SEQ + k0 + pos * 8);
                CP16(dst, src);
            } else {
                c -= 512;
                const int n = c >> 3, pos = c & 7;
                const u32 dst = sb + vtl_off[buf] + (u32)(n * (TST * 2) + pos * 16);
                const char* src = (const char*)(VTgl + (size_t)n * SEQ + k0 + pos * 8);
                CP16(dst, src);
            }
        }
    };

    issue_tile(0, 0);
    CP_COMMIT();

    float acc[2][4][4];
#pragma unroll
    for (int mi = 0; mi < 2; mi++)
#pragma unroll
        for (int ni = 0; ni < 4; ni++)
#pragma unroll
            for (int j = 0; j < 4; j++) acc[mi][ni][j] = 0.0f;

    const int lrow = lane & 15, lhalf = lane >> 4;

    for (int t = 0; t < 32; t++) {
        const int buf = t & 1;
        const int k0 = t * 64;

        CP_WAIT0();
        __syncthreads();   // tile t landed; all warps done with MMA of t-1

        if (t + 1 < 32) {
            issue_tile(t + 1, buf ^ 1);
            CP_COMMIT();
        }

        // process E tile from smem: normalize -> write P to gmem -> split to PH/PL
#pragma unroll
        for (int l = 0; l < 8; l++) {
            const int fid = tid + l * 256;
            const int row = fid >> 4, c4 = (fid & 15) * 4;
            float4 e = *(const float4*)(smm + es_off[buf] + (row * 64 + c4) * 4);
            const float inv = inv_s[row];
            e.x *= inv; e.y *= inv; e.z *= inv; e.w *= inv;
            *(float4*)(Sbase + (size_t)row * SEQ + k0 + c4) = e;   // final attn weights
            __nv_bfloat16 h0, l0, h1, l1, h2, l2, h3, l3;
            split_f(e.x, h0, l0); split_f(e.y, h1, l1);
            split_f(e.z, h2, l2); split_f(e.w, h3, l3);
            const u32 boff = (u32)(row * TST + c4) * 2;
            *(u32*)(smm + PV_PH + boff)     = pack_bf2(h0, h1);
            *(u32*)(smm + PV_PH + boff + 4) = pack_bf2(h2, h3);
            *(u32*)(smm + PV_PL + boff)     = pack_bf2(l0, l1);
            *(u32*)(smm + PV_PL + boff + 4) = pack_bf2(l2, l3);
        }
        __syncthreads();

        // MMA: P (PH/PL) x VT[buf]
#pragma unroll
        for (int ks = 0; ks < 4; ks++) {
            const u32 kcol = (u32)(ks * 16 + lhalf * 8);
            u32 ah[2][4], al[2][4];
#pragma unroll
            for (int mi = 0; mi < 2; mi++) {
                const u32 ro = (u32)((wm * 32 + mi * 16 + lrow) * TST);
                u32 ad = sb + PV_PH + (ro + kcol) * 2;
                LDSM_X4(ah[mi][0], ah[mi][1], ah[mi][2], ah[mi][3], ad);
                ad = sb + PV_PL + (ro + kcol) * 2;
                LDSM_X4(al[mi][0], al[mi][1], al[mi][2], al[mi][3], ad);
            }
            u32 bhf[2][4], blf[2][4];
#pragma unroll
            for (int np = 0; np < 2; np++) {
                const u32 ro = (u32)((wn * 32 + np * 16 + lrow) * TST);
                u32 bd = sb + vth_off[buf] + (ro + kcol) * 2;
                LDSM_X4(bhf[np][0], bhf[np][1], bhf[np][2], bhf[np][3], bd);
                bd = sb + vtl_off[buf] + (ro + kcol) * 2;
                LDSM_X4(blf[np][0], blf[np][1], blf[np][2], blf[np][3], bd);
            }
#pragma unroll
            for (int mi = 0; mi < 2; mi++)
#pragma unroll
                for (int np = 0; np < 2; np++)
#pragma unroll
                    for (int sub = 0; sub < 2; sub++) {
                        const int ni = np * 2 + sub;
                        mma_bf16(acc[mi][ni], ah[mi], bhf[np][sub], bhf[np][sub + 2]);
                        mma_bf16(acc[mi][ni], ah[mi], blf[np][sub], blf[np][sub + 2]);
                        mma_bf16(acc[mi][ni], al[mi], bhf[np][sub], bhf[np][sub + 2]);
                    }
        }
        // next iteration's barrier separates MMA(t) from P/V overwrite(t+1)
    }

    __syncthreads();

    // Epilogue: emit AO as hi/lo bf16
    const int rbase = wm * 32 + (lane >> 2);
    const int cbase = wn * 32 + (lane & 3) * 2;
#pragma unroll
    for (int mi = 0; mi < 2; mi++)
#pragma unroll
        for (int half = 0; half < 2; half++) {
            const int r = rbase + mi * 16 + half * 8;
#pragma unroll
            for (int ni = 0; ni < 4; ni++) {
                const int c = cbase + ni * 8;
                float ox = acc[mi][ni][half * 2];
                float oy = acc[mi][ni][half * 2 + 1];
                __nv_bfloat16 hx, lx, hy, ly;
                split_f(ox, hx, lx); split_f(oy, hy, ly);
                *(u32*)&Obh[(size_t)r * DMODEL + c] = pack_bf2(hx, hy);
                *(u32*)&Obl[(size_t)r * DMODEL + c] = pack_bf2(lx, ly);
            }
        }
}

// ===========================================================================
extern "C" void kernel_launch(void* const* d_in, const int* in_sizes, int n_in,
                              void* d_out, int out_size)
{
    const float* query = (const float*)d_in[0];
    const float* key   = (const float*)d_in[1];
    const float* value = (const float*)d_in[2];
    const float* Wq = (const float*)d_in[3];
    const float* bq = (const float*)d_in[4];
    const float* Wk = (const float*)d_in[5];
    const float* bk = (const float*)d_in[6];
    const float* Wv = (const float*)d_in[7];
    const float* bv = (const float*)d_in[8];
    const float* Wo = (const float*)d_in[9];
    const float* bo = (const float*)d_in[10];

    float* out  = (float*)d_out;
    float* attn = out + (size_t)MTOK * DMODEL;

    __nv_bfloat16 *Xh, *Xl, *WTh, *WTl;
    __nv_bfloat16 *Qh, *Ql, *Kh, *Kl, *Vh, *Vl, *VTh, *VTl, *AOh, *AOl;
    float* rsp;
    cudaGetSymbolAddress((void**)&Xh,  g_Xh);
    cudaGetSymbolAddress((void**)&Xl,  g_Xl);
    cudaGetSymbolAddress((void**)&WTh, g_WTh);
    cudaGetSymbolAddress((void**)&WTl, g_WTl);
    cudaGetSymbolAddress((void**)&Qh,  g_Qh);
    cudaGetSymbolAddress((void**)&Ql,  g_Ql);
    cudaGetSymbolAddress((void**)&Kh,  g_Kh);
    cudaGetSymbolAddress((void**)&Kl,  g_Kl);
    cudaGetSymbolAddress((void**)&Vh,  g_Vh);
    cudaGetSymbolAddress((void**)&Vl,  g_Vl);
    cudaGetSymbolAddress((void**)&VTh, g_VTh);
    cudaGetSymbolAddress((void**)&VTl, g_VTl);
    cudaGetSymbolAddress((void**)&AOh, g_AOh);
    cudaGetSymbolAddress((void**)&AOl, g_AOl);
    cudaGetSymbolAddress((void**)&rsp, g_rowsum);

    static bool attr_done = false;
    if (!attr_done) {
        cudaFuncSetAttribute(proj_bf_kernel<true>,
            cudaFuncAttributeMaxDynamicSharedMemorySize, PJ_SMEM);
        cudaFuncSetAttribute(proj_bf_kernel<false>,
            cudaFuncAttributeMaxDynamicSharedMemorySize, PJ_SMEM);
        cudaFuncSetAttribute(scores_tc_kernel,
            cudaFuncAttributeMaxDynamicSharedMemorySize, SC_SMEM);
        cudaFuncSetAttribute(pv_tc_kernel,
            cudaFuncAttributeMaxDynamicSharedMemorySize, PV_SMEM);
        attr_done = true;
    }

    init_rowsum_kernel<<<(ATTN_ROWS + 255) / 256, 256>>>(rsp);

    const int n4 = MTOK * DMODEL / 4;
    const size_t TD = (size_t)MTOK * DMODEL;
    const size_t WD = (size_t)DMODEL * DMODEL;
    split_input_kernel<<<(n4 + 255) / 256, 256>>>(query, Xh,          Xl,          n4);
    split_input_kernel<<<(n4 + 255) / 256, 256>>>(key,   Xh + TD,     Xl + TD,     n4);
    split_input_kernel<<<(n4 + 255) / 256, 256>>>(value, Xh + 2 * TD, Xl + 2 * TD, n4);
    dim3 wgrid(DMODEL / 32, DMODEL / 32), wblk(32, 8);
    split_weight_kernel<<<wgrid, wblk>>>(Wq, WTh,          WTl);
    split_weight_kernel<<<wgrid, wblk>>>(Wk, WTh + WD,     WTl + WD);
    split_weight_kernel<<<wgrid, wblk>>>(Wv, WTh + 2 * WD, WTl + 2 * WD);
    split_weight_kernel<<<wgrid, wblk>>>(Wo, WTh + 3 * WD, WTl + 3 * WD);

    dim3 gproj(DMODEL / 128, MTOK / 128);  // (6, 64)
    proj_bf_kernel<false><<<gproj, 256, PJ_SMEM>>>(
        Xh,          Xl,          WTh,          WTl,          bq, nullptr, Qh, Ql);
    proj_bf_kernel<false><<<gproj, 256, PJ_SMEM>>>(
        Xh + TD,     Xl + TD,     WTh + WD,     WTl + WD,     bk, nullptr, Kh, Kl);
    proj_bf_kernel<false><<<gproj, 256, PJ_SMEM>>>(
        Xh + 2 * TD, Xl + 2 * TD, WTh + 2 * WD, WTl + 2 * WD, bv, nullptr, Vh, Vl);

    dim3 vtg(SEQ / 32, DK / 32, BATCH * NHEADS);   // (64, 2, 48)
    vtrans_kernel<<<vtg, wblk>>>(Vh, Vl, VTh, VTl);

    dim3 gscores(SEQ / 128, SEQ / 128, BATCH * NHEADS);  // (16, 16, 48)
    scores_tc_kernel<<<gscores, 256, SC_SMEM>>>(Qh, Ql, Kh, Kl, attn, rsp);

    dim3 gpv(1, SEQ / 128, BATCH * NHEADS);  // (1, 16, 48)
    pv_tc_kernel<<<gpv, 256, PV_SMEM>>>(attn, VTh, VTl, AOh, AOl, rsp);

    proj_bf_kernel<true><<<gproj, 256, PJ_SMEM>>>(
        AOh, AOl, WTh + 3 * WD, WTl + 3 * WD, bo, out, nullptr, nullptr);
}